// round 2
// baseline (speedup 1.0000x reference)
#include <cuda_runtime.h>

#define BB 8
#define NN 160
#define DD 128
#define HH 8
#define FF 512
#define ROWS_TOTAL (BB*NN*NN)   // 204800
#define TILE_R 64
#define EPAD 132                // padded E-tile row (floats) to kill bank conflicts

// ---------------- scratch (device globals; allocation-free rule) ----------------
__device__ float g_s_in [BB*NN*NN*HH];   // scores -> (in-place) attn weights, softmax over i
__device__ float g_s_out[BB*NN*NN*HH];   // softmax over j
__device__ float g_v_in [BB*NN*NN*DD];
__device__ float g_v_out[BB*NN*NN*DD];
__device__ float g_out_in [BB*NN*DD];
__device__ float g_out_out[BB*NN*DD];
__device__ float g_xi[BB*NN*DD];
__device__ float g_xj[BB*NN*DD];

// ---------------- packed f32x2 helpers ----------------
__device__ __forceinline__ unsigned long long fma2(unsigned long long a,
                                                   unsigned long long b,
                                                   unsigned long long c) {
    unsigned long long d;
    asm("fma.rn.f32x2 %0, %1, %2, %3;" : "=l"(d) : "l"(a), "l"(b), "l"(c));
    return d;
}
__device__ __forceinline__ float2 uup(unsigned long long a) {
    float2 f;
    asm("mov.b64 {%0, %1}, %2;" : "=f"(f.x), "=f"(f.y) : "l"(a));
    return f;
}

// ---------------- kernel A: fused 6-way edge projection GEMM + scores ----------------
__device__ __forceinline__ void load_w(const float* __restrict__ Wg, float* Ws, int tid) {
    const float4* src = (const float4*)Wg;
    float4* dst = (float4*)Ws;
#pragma unroll
    for (int it = 0; it < 16; it++) dst[tid + it * 256] = src[tid + it * 256];
}

__device__ __forceinline__ void gemm_pass(const float* __restrict__ erow,
                                          const float* __restrict__ Ws,
                                          int c0, unsigned long long (&acc)[16]) {
#pragma unroll
    for (int m = 0; m < 16; m++) acc[m] = 0ULL;
#pragma unroll 4
    for (int k = 0; k < 128; k++) {
        float e = erow[k];
        unsigned long long ep;
        asm("mov.b64 %0, {%1, %1};" : "=l"(ep) : "f"(e));
        const ulonglong2* wrow = (const ulonglong2*)(Ws + k * 128 + c0);
#pragma unroll
        for (int m = 0; m < 8; m++) {
            ulonglong2 w = wrow[m];
            acc[2 * m]     = fma2(ep, w.x, acc[2 * m]);
            acc[2 * m + 1] = fma2(ep, w.y, acc[2 * m + 1]);
        }
    }
}

__device__ __forceinline__ void score_epilogue(const unsigned long long (&accQ)[16],
                                               const unsigned long long (&accK)[16],
                                               const float* __restrict__ bq,
                                               const float* __restrict__ bk,
                                               float* __restrict__ sdst,
                                               long grow, int c0, int cg) {
    float s0 = 0.f, s1 = 0.f;
#pragma unroll
    for (int m = 0; m < 8; m++) {
        float2 q = uup(accQ[m]); float2 kk = uup(accK[m]);
        q.x += bq[c0 + 2 * m];     q.y += bq[c0 + 2 * m + 1];
        kk.x += bk[c0 + 2 * m];    kk.y += bk[c0 + 2 * m + 1];
        s0 += q.x * kk.x + q.y * kk.y;
    }
#pragma unroll
    for (int m = 8; m < 16; m++) {
        float2 q = uup(accQ[m]); float2 kk = uup(accK[m]);
        q.x += bq[c0 + 2 * m];     q.y += bq[c0 + 2 * m + 1];
        kk.x += bk[c0 + 2 * m];    kk.y += bk[c0 + 2 * m + 1];
        s1 += q.x * kk.x + q.y * kk.y;
    }
    int h0 = cg * 2;
    sdst[grow * HH + h0]     = s0 * 0.25f;   // scale = 1/sqrt(16)
    sdst[grow * HH + h0 + 1] = s1 * 0.25f;
}

__device__ __forceinline__ void v_epilogue(const unsigned long long (&acc)[16],
                                           const float* __restrict__ bv,
                                           float* __restrict__ vdst,
                                           long grow, int c0) {
#pragma unroll
    for (int m = 0; m < 16; m++) {
        float2 v = uup(acc[m]);
        v.x += bv[c0 + 2 * m];
        v.y += bv[c0 + 2 * m + 1];
        *(float2*)&vdst[grow * DD + c0 + 2 * m] = v;
    }
}

__global__ void __launch_bounds__(256) edge_gemm_kernel(
    const float* __restrict__ edge,
    const float* __restrict__ Wqi, const float* __restrict__ bqi,
    const float* __restrict__ Wki, const float* __restrict__ bki,
    const float* __restrict__ Wvi, const float* __restrict__ bvi,
    const float* __restrict__ Wqo, const float* __restrict__ bqo,
    const float* __restrict__ Wko, const float* __restrict__ bko,
    const float* __restrict__ Wvo, const float* __restrict__ bvo)
{
    extern __shared__ float sm[];
    float* Es = sm;                     // TILE_R * EPAD
    float* Ws = sm + TILE_R * EPAD;     // 128 * 128
    int tid = threadIdx.x;
    int r = tid >> 2;                   // 0..63 (row in tile)
    int cg = tid & 3;                   // col group
    int c0 = cg * 32;
    long rowbase = (long)blockIdx.x * TILE_R;
    long grow = rowbase + r;

    // load E tile (64 x 128) into padded smem
    const float4* Eg = (const float4*)(edge + rowbase * DD);
#pragma unroll
    for (int it = 0; it < 8; it++) {
        int idx = tid + it * 256;       // float4 index 0..2047
        int rr = idx >> 5; int cc = idx & 31;
        float4 v = Eg[idx];
        *(float4*)&Es[rr * EPAD + cc * 4] = v;
    }
    const float* erow = &Es[r * EPAD];

    unsigned long long accA[16], accB[16];

    // ---- in path ----
    load_w(Wqi, Ws, tid); __syncthreads();
    gemm_pass(erow, Ws, c0, accA);
    __syncthreads(); load_w(Wki, Ws, tid); __syncthreads();
    gemm_pass(erow, Ws, c0, accB);
    score_epilogue(accA, accB, bqi, bki, g_s_in, grow, c0, cg);
    __syncthreads(); load_w(Wvi, Ws, tid); __syncthreads();
    gemm_pass(erow, Ws, c0, accA);
    v_epilogue(accA, bvi, g_v_in, grow, c0);

    // ---- out path ----
    __syncthreads(); load_w(Wqo, Ws, tid); __syncthreads();
    gemm_pass(erow, Ws, c0, accA);
    __syncthreads(); load_w(Wko, Ws, tid); __syncthreads();
    gemm_pass(erow, Ws, c0, accB);
    score_epilogue(accA, accB, bqo, bko, g_s_out, grow, c0, cg);
    __syncthreads(); load_w(Wvo, Ws, tid); __syncthreads();
    gemm_pass(erow, Ws, c0, accA);
    v_epilogue(accA, bvo, g_v_out, grow, c0);
}

// ---------------- kernel B: softmax (warp per group, 160 = 32*5) ----------------
__global__ void softmax_kernel() {
    int gw = blockIdx.x * 8 + (threadIdx.x >> 5);
    int lane = threadIdx.x & 31;
    int which = (gw >= BB * NN * HH) ? 1 : 0;
    int g = which ? gw - BB * NN * HH : gw;
    int b = g / (NN * HH); int rem = g % (NN * HH);
    int x = rem / HH; int h = rem % HH;
    float* s; long base; long stride;
    if (which == 0) { // softmax over i, group (b, j=x, h)
        s = g_s_in;
        base = (long)b * NN * NN * HH + (long)x * HH + h;
        stride = (long)NN * HH;
    } else {          // softmax over j, group (b, i=x, h)
        s = g_s_out;
        base = (long)b * NN * NN * HH + (long)x * NN * HH + h;
        stride = HH;
    }
    float v[5];
#pragma unroll
    for (int t = 0; t < 5; t++) v[t] = s[base + (long)(lane + 32 * t) * stride];
    float mx = v[0];
#pragma unroll
    for (int t = 1; t < 5; t++) mx = fmaxf(mx, v[t]);
#pragma unroll
    for (int o = 16; o > 0; o >>= 1) mx = fmaxf(mx, __shfl_xor_sync(0xffffffffu, mx, o));
    float sum = 0.f;
#pragma unroll
    for (int t = 0; t < 5; t++) { v[t] = __expf(v[t] - mx); sum += v[t]; }
#pragma unroll
    for (int o = 16; o > 0; o >>= 1) sum += __shfl_xor_sync(0xffffffffu, sum, o);
    float inv = __frcp_rn(sum);
#pragma unroll
    for (int t = 0; t < 5; t++) s[base + (long)(lane + 32 * t) * stride] = v[t] * inv;
}

// ---------------- kernel C: attention-weighted reductions ----------------
__global__ void attn_reduce_kernel() {
    int e = threadIdx.x;       // 0..127
    int bn = blockIdx.x;       // (b, n)
    int b = bn / NN; int n = bn % NN;
    int h = e >> 4;
    if (blockIdx.y == 0) {
        // out_in[b, j=n, e] = sum_i a_in[b,i,j,h] * v_in[b,i,j,e]
        float acc = 0.f;
        long abase = (long)b * NN * NN * HH + (long)n * HH + h;
        long vbase = ((long)(b * NN) * NN + n) * DD + e;
#pragma unroll 4
        for (int i = 0; i < NN; i++)
            acc += g_s_in[abase + (long)i * NN * HH] * g_v_in[vbase + (long)i * NN * DD];
        g_out_in[(long)bn * DD + e] = acc;
    } else {
        // out_out[b, i=n, e] = sum_j a_out[b,i,j,h] * v_out[b,i,j,e]
        float acc = 0.f;
        long abase = (long)b * NN * NN * HH + (long)n * NN * HH + h;
        long vbase = ((long)(b * NN + n) * NN) * DD + e;
#pragma unroll 4
        for (int j = 0; j < NN; j++)
            acc += g_s_out[abase + (long)j * HH] * g_v_out[vbase + (long)j * DD];
        g_out_out[(long)bn * DD + e] = acc;
    }
}

// ---------------- kernel D: proj + LN + FFN + LN + edge projections ----------------
__device__ __forceinline__ float block_sum128(float v, volatile float* red) {
    int lane = threadIdx.x & 31, wid = threadIdx.x >> 5;
#pragma unroll
    for (int o = 16; o > 0; o >>= 1) v += __shfl_xor_sync(0xffffffffu, v, o);
    __syncthreads();
    if (lane == 0) red[wid] = v;
    __syncthreads();
    return red[0] + red[1] + red[2] + red[3];
}

__global__ void __launch_bounds__(128) node_kernel(
    const float* __restrict__ node_emb,
    const float* __restrict__ Wpi, const float* __restrict__ bpi,
    const float* __restrict__ Wpo, const float* __restrict__ bpo,
    const float* __restrict__ Wf1, const float* __restrict__ bf1,
    const float* __restrict__ Wf2, const float* __restrict__ bf2,
    const float* __restrict__ g1,  const float* __restrict__ be1,
    const float* __restrict__ g2,  const float* __restrict__ be2,
    const float* __restrict__ Wedge, float* __restrict__ out_x)
{
    __shared__ float s_oi[128], s_oo[128], s_x[128], s_h[512];
    __shared__ float red[4];
    int e = threadIdx.x;
    long row = blockIdx.x;
    s_oi[e] = g_out_in[row * DD + e];
    s_oo[e] = g_out_out[row * DD + e];
    __syncthreads();

    float u = bpi[e] + bpo[e];
#pragma unroll 4
    for (int k = 0; k < 128; k++)
        u += s_oi[k] * Wpi[k * 128 + e] + s_oo[k] * Wpo[k * 128 + e];

    float t = node_emb[row * DD + e] + u;
    float mean = block_sum128(t, red) * (1.0f / 128.0f);
    float dv = t - mean;
    float var = block_sum128(dv * dv, red) * (1.0f / 128.0f);
    float x1 = dv * rsqrtf(var + 1e-5f) * g1[e] + be1[e];
    __syncthreads();
    s_x[e] = x1;
    __syncthreads();

#pragma unroll
    for (int ff = e; ff < 512; ff += 128) {
        float a = bf1[ff];
#pragma unroll 4
        for (int k = 0; k < 128; k++) a += s_x[k] * Wf1[k * 512 + ff];
        s_h[ff] = fmaxf(a, 0.f);
    }
    __syncthreads();
    float y = bf2[e];
#pragma unroll 4
    for (int k = 0; k < 512; k++) y += s_h[k] * Wf2[k * 128 + e];

    float t2 = x1 + y;
    float m2 = block_sum128(t2, red) * (1.0f / 128.0f);
    float dv2 = t2 - m2;
    float v2 = block_sum128(dv2 * dv2, red) * (1.0f / 128.0f);
    float x2 = dv2 * rsqrtf(v2 + 1e-5f) * g2[e] + be2[e];

    out_x[row * DD + e] = x2;
    __syncthreads();
    s_x[e] = x2;
    __syncthreads();

    float xi = 0.f, xj = 0.f;
#pragma unroll 4
    for (int k = 0; k < 128; k++) {
        float xv = s_x[k];
        xi += xv * Wedge[k * 128 + e];
        xj += xv * Wedge[(128 + k) * 128 + e];
    }
    g_xi[row * DD + e] = xi;
    g_xj[row * DD + e] = xj;
}

// ---------------- kernel E: edge_out broadcast ----------------
__global__ void edge_out_kernel(const float* __restrict__ b_edge, float* __restrict__ dst) {
    long gid = (long)blockIdx.x * blockDim.x + threadIdx.x;   // per float4
    int e4 = (int)(gid & 31);
    long rem = gid >> 5;
    int j = (int)(rem % NN);
    long rem2 = rem / NN;
    int i = (int)(rem2 % NN);
    int b = (int)(rem2 / NN);
    float4 xi = ((const float4*)g_xi)[(b * NN + i) * 32 + e4];
    float4 xj = ((const float4*)g_xj)[(b * NN + j) * 32 + e4];
    float4 be = ((const float4*)b_edge)[e4];
    float4 o;
    o.x = xi.x + xj.x + be.x;
    o.y = xi.y + xj.y + be.y;
    o.z = xi.z + xj.z + be.z;
    o.w = xi.w + xj.w + be.w;
    ((float4*)dst)[gid] = o;
}

// ---------------- launch ----------------
extern "C" void kernel_launch(void* const* d_in, const int* in_sizes, int n_in,
                              void* d_out, int out_size) {
    const float* node   = (const float*)d_in[0];
    const float* edge   = (const float*)d_in[1];
    const float* Wqi = (const float*)d_in[2];  const float* bqi = (const float*)d_in[3];
    const float* Wki = (const float*)d_in[4];  const float* bki = (const float*)d_in[5];
    const float* Wvi = (const float*)d_in[6];  const float* bvi = (const float*)d_in[7];
    const float* Wqo = (const float*)d_in[8];  const float* bqo = (const float*)d_in[9];
    const float* Wko = (const float*)d_in[10]; const float* bko = (const float*)d_in[11];
    const float* Wvo = (const float*)d_in[12]; const float* bvo = (const float*)d_in[13];
    const float* Wpi = (const float*)d_in[14]; const float* bpi = (const float*)d_in[15];
    const float* Wpo = (const float*)d_in[16]; const float* bpo = (const float*)d_in[17];
    const float* Wf1 = (const float*)d_in[18]; const float* bf1 = (const float*)d_in[19];
    const float* Wf2 = (const float*)d_in[20]; const float* bf2 = (const float*)d_in[21];
    const float* g1  = (const float*)d_in[22]; const float* be1 = (const float*)d_in[23];
    const float* g2  = (const float*)d_in[24]; const float* be2 = (const float*)d_in[25];
    const float* Wedge = (const float*)d_in[26];
    const float* bedge = (const float*)d_in[27];
    float* out = (float*)d_out;

    size_t smemA = (size_t)(TILE_R * EPAD + 128 * 128) * sizeof(float);  // 99328 B
    cudaFuncSetAttribute(edge_gemm_kernel,
                         cudaFuncAttributeMaxDynamicSharedMemorySize, (int)smemA);

    edge_gemm_kernel<<<ROWS_TOTAL / TILE_R, 256, smemA>>>(
        edge, Wqi, bqi, Wki, bki, Wvi, bvi, Wqo, bqo, Wko, bko, Wvo, bvo);

    softmax_kernel<<<(2 * BB * NN * HH) / 8, 256>>>();

    attn_reduce_kernel<<<dim3(BB * NN, 2), 128>>>();

    node_kernel<<<BB * NN, 128>>>(node, Wpi, bpi, Wpo, bpo, Wf1, bf1, Wf2, bf2,
                                  g1, be1, g2, be2, Wedge, out);

    edge_out_kernel<<<(BB * NN * NN * DD / 4) / 256, 256>>>(bedge, out + BB * NN * DD);
}

// round 3
// speedup vs baseline: 8.6057x; 8.6057x over previous
#include <cuda_runtime.h>
#include <cstdint>

#define BB 8
#define NN 160
#define DD 128
#define HH 8
#define ROWS_TOTAL (BB*NN*NN)   // 204800

// ---------------- scratch (device globals; allocation-free rule) ----------------
__device__ float g_s_in [ROWS_TOTAL*HH];     // scores -> attn weights (softmax over i)
__device__ float g_s_out[ROWS_TOTAL*HH];     // softmax over j
__device__ float g_v_in [ROWS_TOTAL*DD];     // v (bias included)
__device__ float g_v_out[ROWS_TOTAL*DD];
__device__ float g_out_in [BB*NN*DD];
__device__ float g_out_out[BB*NN*DD];
__device__ float g_xi[BB*NN*DD];
__device__ float g_xj[BB*NN*DD];

// ---------------- 3xTF32 helpers ----------------
__device__ __forceinline__ void cvt2(float x, float& hi, float& lo) {
    uint32_t h; asm("cvt.rna.tf32.f32 %0, %1;" : "=r"(h) : "f"(x));
    hi = __uint_as_float(h);
    float r = x - hi;
    uint32_t l; asm("cvt.rna.tf32.f32 %0, %1;" : "=r"(l) : "f"(r));
    lo = __uint_as_float(l);
}

#define MMA_TF32(d, a, b)                                                   \
    asm("mma.sync.aligned.m16n8k8.row.col.f32.tf32.tf32.f32 "               \
        "{%0,%1,%2,%3}, {%4,%5,%6,%7}, {%8,%9}, {%0,%1,%2,%3};"             \
        : "+f"(d[0]), "+f"(d[1]), "+f"(d[2]), "+f"(d[3])                    \
        : "r"(a[0]), "r"(a[1]), "r"(a[2]), "r"(a[3]), "r"(b[0]), "r"(b[1]))

// ---------------- GEMM pieces ----------------
// smem layout (floats): Ahi[64*132], Alo[64*132], Bhi[128*132], Blo[128*132]
#define A_STRIDE 132
#define SM_AHI 0
#define SM_ALO 8448
#define SM_BHI 16896
#define SM_BLO 33792
#define SM_FLOATS 50688          // 202752 bytes

__device__ __forceinline__ void load_w_hilo(const float* __restrict__ W,
                                            float* Bh, float* Bl, int tid) {
    const float4* Wg = (const float4*)W;
#pragma unroll
    for (int it = 0; it < 16; it++) {
        int idx = tid + it * 256;         // 4096 float4 total
        int r = idx >> 5, c4 = idx & 31;
        float4 v = Wg[idx];
        float4 h, l;
        cvt2(v.x, h.x, l.x); cvt2(v.y, h.y, l.y);
        cvt2(v.z, h.z, l.z); cvt2(v.w, h.w, l.w);
        *(float4*)&Bh[r * A_STRIDE + c4 * 4] = h;
        *(float4*)&Bl[r * A_STRIDE + c4 * 4] = l;
    }
}

__device__ __forceinline__ void mma_pass(const float* __restrict__ Ah,
                                         const float* __restrict__ Al,
                                         const float* __restrict__ Bh,
                                         const float* __restrict__ Bl,
                                         int R0, int C0, int g, int tg,
                                         float (&acc)[2][4][4]) {
#pragma unroll
    for (int i = 0; i < 2; i++)
#pragma unroll
        for (int j = 0; j < 4; j++)
#pragma unroll
            for (int t = 0; t < 4; t++) acc[i][j][t] = 0.f;

#pragma unroll 2
    for (int ks = 0; ks < 16; ks++) {
        int k0 = ks * 8;
        uint32_t ah[2][4], al[2][4];
#pragma unroll
        for (int i = 0; i < 2; i++) {
            int r0 = (R0 + 16 * i + g) * A_STRIDE + k0 + tg;
            int r1 = (R0 + 16 * i + 8 + g) * A_STRIDE + k0 + tg;
            ah[i][0] = __float_as_uint(Ah[r0]);
            ah[i][1] = __float_as_uint(Ah[r1]);
            ah[i][2] = __float_as_uint(Ah[r0 + 4]);
            ah[i][3] = __float_as_uint(Ah[r1 + 4]);
            al[i][0] = __float_as_uint(Al[r0]);
            al[i][1] = __float_as_uint(Al[r1]);
            al[i][2] = __float_as_uint(Al[r0 + 4]);
            al[i][3] = __float_as_uint(Al[r1 + 4]);
        }
        uint32_t bh[4][2], bl[4][2];
#pragma unroll
        for (int j = 0; j < 4; j++) {
            int cb = C0 + 8 * j + g;
            bh[j][0] = __float_as_uint(Bh[(k0 + tg) * A_STRIDE + cb]);
            bh[j][1] = __float_as_uint(Bh[(k0 + tg + 4) * A_STRIDE + cb]);
            bl[j][0] = __float_as_uint(Bl[(k0 + tg) * A_STRIDE + cb]);
            bl[j][1] = __float_as_uint(Bl[(k0 + tg + 4) * A_STRIDE + cb]);
        }
#pragma unroll
        for (int i = 0; i < 2; i++)
#pragma unroll
            for (int j = 0; j < 4; j++) {
                MMA_TF32(acc[i][j], ah[i], bh[j]);
                MMA_TF32(acc[i][j], ah[i], bl[j]);
                MMA_TF32(acc[i][j], al[i], bh[j]);
            }
    }
}

// fragment C mapping (m16n8k8): c0:(g, 2tg) c1:(g, 2tg+1) c2:(g+8, 2tg) c3:(g+8, 2tg+1)
__device__ __forceinline__ void score_ep(const float (&aq)[2][4][4],
                                         const float (&ak)[2][4][4],
                                         const float* __restrict__ bq,
                                         const float* __restrict__ bk,
                                         float* __restrict__ sdst,
                                         long rowbase, int R0, int C0,
                                         int g, int tg) {
    float p[2][2][2];   // [mtile][rowhalf][head-in-warp]
#pragma unroll
    for (int i = 0; i < 2; i++)
#pragma unroll
        for (int h = 0; h < 2; h++) { p[i][0][h] = 0.f; p[i][1][h] = 0.f; }

#pragma unroll
    for (int i = 0; i < 2; i++)
#pragma unroll
        for (int j = 0; j < 4; j++) {
            int c = C0 + 8 * j + 2 * tg;
            float bq0 = bq[c], bq1 = bq[c + 1];
            float bk0 = bk[c], bk1 = bk[c + 1];
            int hh = j >> 1;
            float q0 = aq[i][j][0] + bq0, q1 = aq[i][j][1] + bq1;
            float k0 = ak[i][j][0] + bk0, k1 = ak[i][j][1] + bk1;
            p[i][0][hh] += q0 * k0 + q1 * k1;
            q0 = aq[i][j][2] + bq0; q1 = aq[i][j][3] + bq1;
            k0 = ak[i][j][2] + bk0; k1 = ak[i][j][3] + bk1;
            p[i][1][hh] += q0 * k0 + q1 * k1;
        }
#pragma unroll
    for (int i = 0; i < 2; i++)
#pragma unroll
        for (int hf = 0; hf < 2; hf++)
#pragma unroll
            for (int hh = 0; hh < 2; hh++) {
                float v = p[i][hf][hh];
                v += __shfl_xor_sync(0xffffffffu, v, 1);
                v += __shfl_xor_sync(0xffffffffu, v, 2);
                p[i][hf][hh] = v;
            }
    if (tg == 0) {
#pragma unroll
        for (int i = 0; i < 2; i++)
#pragma unroll
            for (int hf = 0; hf < 2; hf++)
#pragma unroll
                for (int hh = 0; hh < 2; hh++) {
                    long row = rowbase + R0 + 16 * i + 8 * hf + g;
                    sdst[row * HH + (C0 >> 4) + hh] = p[i][hf][hh] * 0.25f;
                }
    }
}

__device__ __forceinline__ void v_ep(const float (&acc)[2][4][4],
                                     const float* __restrict__ bv,
                                     float* __restrict__ vdst,
                                     long rowbase, int R0, int C0,
                                     int g, int tg) {
#pragma unroll
    for (int i = 0; i < 2; i++)
#pragma unroll
        for (int j = 0; j < 4; j++) {
            int c = C0 + 8 * j + 2 * tg;
            float bv0 = bv[c], bv1 = bv[c + 1];
            long r0 = rowbase + R0 + 16 * i + g;
            long r1 = r0 + 8;
            float2 v0 = make_float2(acc[i][j][0] + bv0, acc[i][j][1] + bv1);
            float2 v1 = make_float2(acc[i][j][2] + bv0, acc[i][j][3] + bv1);
            *(float2*)&vdst[r0 * DD + c] = v0;
            *(float2*)&vdst[r1 * DD + c] = v1;
        }
}

__global__ void __launch_bounds__(256) fused_edge_kernel(
    const float* __restrict__ edge,
    const float* __restrict__ Wqi, const float* __restrict__ bqi,
    const float* __restrict__ Wki, const float* __restrict__ bki,
    const float* __restrict__ Wvi, const float* __restrict__ bvi,
    const float* __restrict__ Wqo, const float* __restrict__ bqo,
    const float* __restrict__ Wko, const float* __restrict__ bko,
    const float* __restrict__ Wvo, const float* __restrict__ bvo)
{
    extern __shared__ float sm[];
    float* Ahi = sm + SM_AHI;
    float* Alo = sm + SM_ALO;
    float* Bhi = sm + SM_BHI;
    float* Blo = sm + SM_BLO;
    int tid = threadIdx.x;
    int lane = tid & 31, wid = tid >> 5;
    int g = lane >> 2, tg = lane & 3;
    int wr = wid >> 2, wc = wid & 3;
    int R0 = wr * 32, C0 = wc * 32;
    long rowbase = (long)blockIdx.x * 64;

    // load + convert E tile (64 x 128)
    const float4* Eg = (const float4*)(edge + rowbase * DD);
#pragma unroll
    for (int it = 0; it < 8; it++) {
        int idx = tid + it * 256;         // 2048 float4
        int r = idx >> 5, c4 = idx & 31;
        float4 v = Eg[idx];
        float4 h, l;
        cvt2(v.x, h.x, l.x); cvt2(v.y, h.y, l.y);
        cvt2(v.z, h.z, l.z); cvt2(v.w, h.w, l.w);
        *(float4*)&Ahi[r * A_STRIDE + c4 * 4] = h;
        *(float4*)&Alo[r * A_STRIDE + c4 * 4] = l;
    }

    float accq[2][4][4], acck[2][4][4];

#pragma unroll 1
    for (int p = 0; p < 2; p++) {
        const float* Wq = p ? Wqo : Wqi;  const float* bq = p ? bqo : bqi;
        const float* Wk = p ? Wko : Wki;  const float* bk = p ? bko : bki;
        const float* Wv = p ? Wvo : Wvi;  const float* bv = p ? bvo : bvi;
        float* sdst = p ? g_s_out : g_s_in;
        float* vdst = p ? g_v_out : g_v_in;

        __syncthreads();                       // prior readers of B done (also covers E load at p=0)
        load_w_hilo(Wq, Bhi, Blo, tid);
        __syncthreads();
        mma_pass(Ahi, Alo, Bhi, Blo, R0, C0, g, tg, accq);

        __syncthreads();
        load_w_hilo(Wk, Bhi, Blo, tid);
        __syncthreads();
        mma_pass(Ahi, Alo, Bhi, Blo, R0, C0, g, tg, acck);

        score_ep(accq, acck, bq, bk, sdst, rowbase, R0, C0, g, tg);

        __syncthreads();
        load_w_hilo(Wv, Bhi, Blo, tid);
        __syncthreads();
        mma_pass(Ahi, Alo, Bhi, Blo, R0, C0, g, tg, accq);
        v_ep(accq, bv, vdst, rowbase, R0, C0, g, tg);
    }
}

// ---------------- softmax (warp per group, 160 = 32*5) ----------------
__global__ void softmax_kernel() {
    int gw = blockIdx.x * 8 + (threadIdx.x >> 5);
    int lane = threadIdx.x & 31;
    int which = (gw >= BB * NN * HH) ? 1 : 0;
    int g = which ? gw - BB * NN * HH : gw;
    int b = g / (NN * HH); int rem = g % (NN * HH);
    int x = rem / HH; int h = rem % HH;
    float* s; long base; long stride;
    if (which == 0) { // softmax over i, group (b, j=x, h)
        s = g_s_in;
        base = (long)b * NN * NN * HH + (long)x * HH + h;
        stride = (long)NN * HH;
    } else {          // softmax over j, group (b, i=x, h)
        s = g_s_out;
        base = (long)b * NN * NN * HH + (long)x * NN * HH + h;
        stride = HH;
    }
    float v[5];
#pragma unroll
    for (int t = 0; t < 5; t++) v[t] = s[base + (long)(lane + 32 * t) * stride];
    float mx = v[0];
#pragma unroll
    for (int t = 1; t < 5; t++) mx = fmaxf(mx, v[t]);
#pragma unroll
    for (int o = 16; o > 0; o >>= 1) mx = fmaxf(mx, __shfl_xor_sync(0xffffffffu, mx, o));
    float sum = 0.f;
#pragma unroll
    for (int t = 0; t < 5; t++) { v[t] = __expf(v[t] - mx); sum += v[t]; }
#pragma unroll
    for (int o = 16; o > 0; o >>= 1) sum += __shfl_xor_sync(0xffffffffu, sum, o);
    float inv = __frcp_rn(sum);
#pragma unroll
    for (int t = 0; t < 5; t++) s[base + (long)(lane + 32 * t) * stride] = v[t] * inv;
}

// ---------------- attention-weighted reductions ----------------
__global__ void attn_reduce_kernel() {
    int e = threadIdx.x;       // 0..127
    int bn = blockIdx.x;       // (b, n)
    int b = bn / NN; int n = bn % NN;
    int h = e >> 4;
    if (blockIdx.y == 0) {
        float acc = 0.f;
        long abase = (long)b * NN * NN * HH + (long)n * HH + h;
        long vbase = ((long)(b * NN) * NN + n) * DD + e;
#pragma unroll 4
        for (int i = 0; i < NN; i++)
            acc += g_s_in[abase + (long)i * NN * HH] * g_v_in[vbase + (long)i * NN * DD];
        g_out_in[(long)bn * DD + e] = acc;
    } else {
        float acc = 0.f;
        long abase = (long)b * NN * NN * HH + (long)n * NN * HH + h;
        long vbase = ((long)(b * NN + n) * NN) * DD + e;
#pragma unroll 4
        for (int j = 0; j < NN; j++)
            acc += g_s_out[abase + (long)j * HH] * g_v_out[vbase + (long)j * DD];
        g_out_out[(long)bn * DD + e] = acc;
    }
}

// ---------------- node: proj + LN + FFN + LN + edge projections (4 rows/block) ----------------
__device__ __forceinline__ float2 bsum2(float2 v, float (*red)[2], int lane, int wid) {
#pragma unroll
    for (int o = 16; o > 0; o >>= 1) {
        v.x += __shfl_xor_sync(0xffffffffu, v.x, o);
        v.y += __shfl_xor_sync(0xffffffffu, v.y, o);
    }
    if (lane == 0) { red[wid][0] = v.x; red[wid][1] = v.y; }
    __syncthreads();
    int base = (wid >> 2) << 2;
    float2 o2;
    o2.x = red[base][0] + red[base + 1][0] + red[base + 2][0] + red[base + 3][0];
    o2.y = red[base][1] + red[base + 1][1] + red[base + 2][1] + red[base + 3][1];
    __syncthreads();
    return o2;
}

__global__ void __launch_bounds__(256) node_kernel(
    const float* __restrict__ node_emb,
    const float* __restrict__ Wpi, const float* __restrict__ bpi,
    const float* __restrict__ Wpo, const float* __restrict__ bpo,
    const float* __restrict__ Wf1, const float* __restrict__ bf1,
    const float* __restrict__ Wf2, const float* __restrict__ bf2,
    const float* __restrict__ g1,  const float* __restrict__ be1,
    const float* __restrict__ g2,  const float* __restrict__ be2,
    const float* __restrict__ Wedge, float* __restrict__ out_x)
{
    __shared__ float s_oi[4][128], s_oo[4][128], s_x[4][128], s_h[4][512];
    __shared__ float red[8][2];
    int tid = threadIdx.x;
    int e = tid & 127;
    int rh = tid >> 7;        // 0/1 -> rows {0,1} / {2,3}
    int lane = tid & 31, wid = tid >> 5;
    int r0 = rh * 2;
    long row0 = (long)blockIdx.x * 4;

#pragma unroll
    for (int q = 0; q < 2; q++) {
        s_oi[r0 + q][e] = g_out_in[(row0 + r0 + q) * DD + e];
        s_oo[r0 + q][e] = g_out_out[(row0 + r0 + q) * DD + e];
    }
    __syncthreads();

    float u0 = bpi[e] + bpo[e], u1 = u0;
#pragma unroll 4
    for (int k = 0; k < 128; k++) {
        float w1 = Wpi[k * 128 + e], w2 = Wpo[k * 128 + e];
        u0 += s_oi[r0][k] * w1 + s_oo[r0][k] * w2;
        u1 += s_oi[r0 + 1][k] * w1 + s_oo[r0 + 1][k] * w2;
    }
    float t0 = node_emb[(row0 + r0) * DD + e] + u0;
    float t1 = node_emb[(row0 + r0 + 1) * DD + e] + u1;

    float2 s = bsum2(make_float2(t0, t1), red, lane, wid);
    float d0 = t0 - s.x * (1.f / 128.f);
    float d1 = t1 - s.y * (1.f / 128.f);
    float2 vs = bsum2(make_float2(d0 * d0, d1 * d1), red, lane, wid);
    float x0 = d0 * rsqrtf(vs.x * (1.f / 128.f) + 1e-5f) * g1[e] + be1[e];
    float x1 = d1 * rsqrtf(vs.y * (1.f / 128.f) + 1e-5f) * g1[e] + be1[e];
    s_x[r0][e] = x0; s_x[r0 + 1][e] = x1;
    __syncthreads();

#pragma unroll
    for (int c = 0; c < 4; c++) {
        int ff = e + 128 * c;
        float a0 = bf1[ff], a1 = a0;
#pragma unroll 4
        for (int k = 0; k < 128; k++) {
            float w = Wf1[k * 512 + ff];
            a0 += s_x[r0][k] * w; a1 += s_x[r0 + 1][k] * w;
        }
        s_h[r0][ff] = fmaxf(a0, 0.f);
        s_h[r0 + 1][ff] = fmaxf(a1, 0.f);
    }
    __syncthreads();

    float y0 = bf2[e], y1 = y0;
#pragma unroll 4
    for (int k = 0; k < 512; k++) {
        float w = Wf2[k * 128 + e];
        y0 += s_h[r0][k] * w; y1 += s_h[r0 + 1][k] * w;
    }
    float t20 = x0 + y0, t21 = x1 + y1;
    float2 s2 = bsum2(make_float2(t20, t21), red, lane, wid);
    float n0 = t20 - s2.x * (1.f / 128.f);
    float n1 = t21 - s2.y * (1.f / 128.f);
    float2 v2 = bsum2(make_float2(n0 * n0, n1 * n1), red, lane, wid);
    float z0 = n0 * rsqrtf(v2.x * (1.f / 128.f) + 1e-5f) * g2[e] + be2[e];
    float z1 = n1 * rsqrtf(v2.y * (1.f / 128.f) + 1e-5f) * g2[e] + be2[e];
    out_x[(row0 + r0) * DD + e] = z0;
    out_x[(row0 + r0 + 1) * DD + e] = z1;
    __syncthreads();
    s_x[r0][e] = z0; s_x[r0 + 1][e] = z1;
    __syncthreads();

    float xi0 = 0.f, xi1 = 0.f, xj0 = 0.f, xj1 = 0.f;
#pragma unroll 4
    for (int k = 0; k < 128; k++) {
        float w1 = Wedge[k * 128 + e], w2 = Wedge[(128 + k) * 128 + e];
        float a = s_x[r0][k], b = s_x[r0 + 1][k];
        xi0 += a * w1; xi1 += b * w1;
        xj0 += a * w2; xj1 += b * w2;
    }
    g_xi[(row0 + r0) * DD + e] = xi0; g_xi[(row0 + r0 + 1) * DD + e] = xi1;
    g_xj[(row0 + r0) * DD + e] = xj0; g_xj[(row0 + r0 + 1) * DD + e] = xj1;
}

// ---------------- edge_out broadcast ----------------
__global__ void edge_out_kernel(const float* __restrict__ b_edge, float* __restrict__ dst) {
    long gid = (long)blockIdx.x * blockDim.x + threadIdx.x;   // per float4
    int e4 = (int)(gid & 31);
    long rem = gid >> 5;
    int j = (int)(rem % NN);
    long rem2 = rem / NN;
    int i = (int)(rem2 % NN);
    int b = (int)(rem2 / NN);
    float4 xi = ((const float4*)g_xi)[(b * NN + i) * 32 + e4];
    float4 xj = ((const float4*)g_xj)[(b * NN + j) * 32 + e4];
    float4 be = ((const float4*)b_edge)[e4];
    float4 o;
    o.x = xi.x + xj.x + be.x;
    o.y = xi.y + xj.y + be.y;
    o.z = xi.z + xj.z + be.z;
    o.w = xi.w + xj.w + be.w;
    ((float4*)dst)[gid] = o;
}

// ---------------- launch ----------------
extern "C" void kernel_launch(void* const* d_in, const int* in_sizes, int n_in,
                              void* d_out, int out_size) {
    const float* node   = (const float*)d_in[0];
    const float* edge   = (const float*)d_in[1];
    const float* Wqi = (const float*)d_in[2];  const float* bqi = (const float*)d_in[3];
    const float* Wki = (const float*)d_in[4];  const float* bki = (const float*)d_in[5];
    const float* Wvi = (const float*)d_in[6];  const float* bvi = (const float*)d_in[7];
    const float* Wqo = (const float*)d_in[8];  const float* bqo = (const float*)d_in[9];
    const float* Wko = (const float*)d_in[10]; const float* bko = (const float*)d_in[11];
    const float* Wvo = (const float*)d_in[12]; const float* bvo = (const float*)d_in[13];
    const float* Wpi = (const float*)d_in[14]; const float* bpi = (const float*)d_in[15];
    const float* Wpo = (const float*)d_in[16]; const float* bpo = (const float*)d_in[17];
    const float* Wf1 = (const float*)d_in[18]; const float* bf1 = (const float*)d_in[19];
    const float* Wf2 = (const float*)d_in[20]; const float* bf2 = (const float*)d_in[21];
    const float* g1  = (const float*)d_in[22]; const float* be1 = (const float*)d_in[23];
    const float* g2  = (const float*)d_in[24]; const float* be2 = (const float*)d_in[25];
    const float* Wedge = (const float*)d_in[26];
    const float* bedge = (const float*)d_in[27];
    float* out = (float*)d_out;

    size_t smemA = SM_FLOATS * sizeof(float);   // 202752 B
    cudaFuncSetAttribute(fused_edge_kernel,
                         cudaFuncAttributeMaxDynamicSharedMemorySize, (int)smemA);

    fused_edge_kernel<<<ROWS_TOTAL / 64, 256, smemA>>>(
        edge, Wqi, bqi, Wki, bki, Wvi, bvi, Wqo, bqo, Wko, bko, Wvo, bvo);

    softmax_kernel<<<(2 * BB * NN * HH) / 8, 256>>>();

    attn_reduce_kernel<<<dim3(BB * NN, 2), 128>>>();

    node_kernel<<<BB * NN / 4, 256>>>(node, Wpi, bpi, Wpo, bpo, Wf1, bf1, Wf2, bf2,
                                      g1, be1, g2, be2, Wedge, out);

    edge_out_kernel<<<(BB * NN * NN * DD / 4) / 256, 256>>>(bedge, out + BB * NN * DD);
}

// round 4
// speedup vs baseline: 17.2347x; 2.0027x over previous
#include <cuda_runtime.h>
#include <cstdint>

#define BB 8
#define NN 160
#define DD 128
#define HH 8
#define ROWS_TOTAL (BB*NN*NN)   // 204800

// ---------------- scratch (device globals; allocation-free rule) ----------------
__device__ float g_s_in [ROWS_TOTAL*HH];     // [b, j, h, i] contiguous in i
__device__ float g_s_out[ROWS_TOTAL*HH];     // [b, i, h, j] contiguous in j
__device__ float g_v_in [ROWS_TOTAL*DD];
__device__ float g_v_out[ROWS_TOTAL*DD];
__device__ float g_out_in [BB*NN*DD];
__device__ float g_out_out[BB*NN*DD];
__device__ float g_tmp1[BB*NN*DD];           // t / t2
__device__ float g_x1  [BB*NN*DD];
__device__ float g_ff  [BB*NN*512];
__device__ float g_xi[BB*NN*DD];
__device__ float g_xj[BB*NN*DD];

// ---------------- tf32 helpers ----------------
__device__ __forceinline__ float cvt1(float x) {
    uint32_t u; asm("cvt.rna.tf32.f32 %0, %1;" : "=r"(u) : "f"(x));
    return __uint_as_float(u);
}

#define MMA_TF32(d, a, b)                                                   \
    asm("mma.sync.aligned.m16n8k8.row.col.f32.tf32.tf32.f32 "               \
        "{%0,%1,%2,%3}, {%4,%5,%6,%7}, {%8,%9}, {%0,%1,%2,%3};"             \
        : "+f"(d[0]), "+f"(d[1]), "+f"(d[2]), "+f"(d[3])                    \
        : "r"(a[0]), "r"(a[1]), "r"(a[2]), "r"(a[3]), "r"(b[0]), "r"(b[1]))

#define A_STRIDE 132
#define SMEM_FLOATS (64*A_STRIDE + 128*A_STRIDE)   // 25344 floats = 101376 B

// one 128-deep K chunk of mma: A tile 64x128 (As), B tile 128x128 (Bs), accumulate
__device__ __forceinline__ void mma_chunk(const float* As, const float* Bs,
                                          int R0, int C0, int g, int tg,
                                          float (&acc)[2][4][4]) {
#pragma unroll 4
    for (int ks = 0; ks < 16; ks++) {
        int k0 = ks * 8;
        uint32_t a[2][4];
#pragma unroll
        for (int i = 0; i < 2; i++) {
            int r0 = (R0 + 16 * i + g) * A_STRIDE + k0 + tg;
            int r1 = r0 + 8 * A_STRIDE;
            a[i][0] = __float_as_uint(As[r0]);
            a[i][1] = __float_as_uint(As[r1]);
            a[i][2] = __float_as_uint(As[r0 + 4]);
            a[i][3] = __float_as_uint(As[r1 + 4]);
        }
        uint32_t b[4][2];
#pragma unroll
        for (int j = 0; j < 4; j++) {
            int cb = C0 + 8 * j + g;
            b[j][0] = __float_as_uint(Bs[(k0 + tg) * A_STRIDE + cb]);
            b[j][1] = __float_as_uint(Bs[(k0 + tg + 4) * A_STRIDE + cb]);
        }
#pragma unroll
        for (int i = 0; i < 2; i++)
#pragma unroll
            for (int j = 0; j < 4; j++)
                MMA_TF32(acc[i][j], a[i], b[j]);
    }
}

__device__ __forceinline__ void zero_acc(float (&acc)[2][4][4]) {
#pragma unroll
    for (int i = 0; i < 2; i++)
#pragma unroll
        for (int j = 0; j < 4; j++)
#pragma unroll
            for (int t = 0; t < 4; t++) acc[i][j][t] = 0.f;
}

// ---------------- fused edge kernel ----------------
__device__ __forceinline__ void load_w128(const float* __restrict__ W, float* Bs, int tid) {
    const float4* Wg = (const float4*)W;
#pragma unroll
    for (int it = 0; it < 16; it++) {
        int idx = tid + it * 256;         // 4096 float4
        int r = idx >> 5, c4 = idx & 31;
        float4 v = Wg[idx];
        float4 h;
        h.x = cvt1(v.x); h.y = cvt1(v.y); h.z = cvt1(v.z); h.w = cvt1(v.w);
        *(float4*)&Bs[r * A_STRIDE + c4 * 4] = h;
    }
}

// frag C map: c0:(g,2tg) c1:(g,2tg+1) c2:(g+8,2tg) c3:(g+8,2tg+1) rel (R0+16i, C0+8j)
__device__ __forceinline__ void score_ep(const float (&aq)[2][4][4],
                                         const float (&ak)[2][4][4],
                                         const float* __restrict__ bq,
                                         const float* __restrict__ bk,
                                         float* __restrict__ sdst, int swap,
                                         int rowbase, int R0, int C0,
                                         int g, int tg) {
    float p[2][2][2];
#pragma unroll
    for (int i = 0; i < 2; i++)
#pragma unroll
        for (int h = 0; h < 2; h++) { p[i][0][h] = 0.f; p[i][1][h] = 0.f; }

#pragma unroll
    for (int i = 0; i < 2; i++)
#pragma unroll
        for (int j = 0; j < 4; j++) {
            int c = C0 + 8 * j + 2 * tg;
            float bq0 = bq[c], bq1 = bq[c + 1];
            float bk0 = bk[c], bk1 = bk[c + 1];
            int hh = j >> 1;
            float q0 = aq[i][j][0] + bq0, q1 = aq[i][j][1] + bq1;
            float k0 = ak[i][j][0] + bk0, k1 = ak[i][j][1] + bk1;
            p[i][0][hh] += q0 * k0 + q1 * k1;
            q0 = aq[i][j][2] + bq0; q1 = aq[i][j][3] + bq1;
            k0 = ak[i][j][2] + bk0; k1 = ak[i][j][3] + bk1;
            p[i][1][hh] += q0 * k0 + q1 * k1;
        }
#pragma unroll
    for (int i = 0; i < 2; i++)
#pragma unroll
        for (int hf = 0; hf < 2; hf++)
#pragma unroll
            for (int hh = 0; hh < 2; hh++) {
                float v = p[i][hf][hh];
                v += __shfl_xor_sync(0xffffffffu, v, 1);
                v += __shfl_xor_sync(0xffffffffu, v, 2);
                p[i][hf][hh] = v;
            }
    if (tg == 0) {
#pragma unroll
        for (int i = 0; i < 2; i++)
#pragma unroll
            for (int hf = 0; hf < 2; hf++)
#pragma unroll
                for (int hh = 0; hh < 2; hh++) {
                    int grow = rowbase + R0 + 16 * i + 8 * hf + g;
                    int b = grow / (NN * NN);
                    int rem = grow - b * NN * NN;
                    int ii = rem / NN;
                    int jj = rem - ii * NN;
                    int h = (C0 >> 4) + hh;
                    int r1 = swap ? jj : ii;
                    int r2 = swap ? ii : jj;
                    sdst[((long)(b * NN + r1) * HH + h) * NN + r2] =
                        p[i][hf][hh] * 0.25f;
                }
    }
}

__device__ __forceinline__ void v_ep(const float (&acc)[2][4][4],
                                     const float* __restrict__ bv,
                                     float* __restrict__ vdst,
                                     long rowbase, int R0, int C0,
                                     int g, int tg) {
#pragma unroll
    for (int i = 0; i < 2; i++)
#pragma unroll
        for (int j = 0; j < 4; j++) {
            int c = C0 + 8 * j + 2 * tg;
            float bv0 = bv[c], bv1 = bv[c + 1];
            long r0 = rowbase + R0 + 16 * i + g;
            long r1 = r0 + 8;
            *(float2*)&vdst[r0 * DD + c] = make_float2(acc[i][j][0] + bv0, acc[i][j][1] + bv1);
            *(float2*)&vdst[r1 * DD + c] = make_float2(acc[i][j][2] + bv0, acc[i][j][3] + bv1);
        }
}

__global__ void __launch_bounds__(256) fused_edge_kernel(
    const float* __restrict__ edge,
    const float* __restrict__ Wqi, const float* __restrict__ bqi,
    const float* __restrict__ Wki, const float* __restrict__ bki,
    const float* __restrict__ Wvi, const float* __restrict__ bvi,
    const float* __restrict__ Wqo, const float* __restrict__ bqo,
    const float* __restrict__ Wko, const float* __restrict__ bko,
    const float* __restrict__ Wvo, const float* __restrict__ bvo)
{
    extern __shared__ float sm[];
    float* As = sm;
    float* Bs = sm + 64 * A_STRIDE;
    int tid = threadIdx.x;
    int lane = tid & 31, wid = tid >> 5;
    int g = lane >> 2, tg = lane & 3;
    int R0 = (wid >> 2) * 32, C0 = (wid & 3) * 32;
    int rowbase = blockIdx.x * 64;

    // load + convert E tile (64 x 128)
    const float4* Eg = (const float4*)(edge + (long)rowbase * DD);
#pragma unroll
    for (int it = 0; it < 8; it++) {
        int idx = tid + it * 256;
        int r = idx >> 5, c4 = idx & 31;
        float4 v = Eg[idx];
        float4 h;
        h.x = cvt1(v.x); h.y = cvt1(v.y); h.z = cvt1(v.z); h.w = cvt1(v.w);
        *(float4*)&As[r * A_STRIDE + c4 * 4] = h;
    }

    float accq[2][4][4], acck[2][4][4];

#pragma unroll 1
    for (int p = 0; p < 2; p++) {
        const float* Wq = p ? Wqo : Wqi;  const float* bq = p ? bqo : bqi;
        const float* Wk = p ? Wko : Wki;  const float* bk = p ? bko : bki;
        const float* Wv = p ? Wvo : Wvi;  const float* bv = p ? bvo : bvi;
        float* sdst = p ? g_s_out : g_s_in;
        float* vdst = p ? g_v_out : g_v_in;
        int swap = (p == 0);

        __syncthreads();
        load_w128(Wq, Bs, tid);
        __syncthreads();
        zero_acc(accq);
        mma_chunk(As, Bs, R0, C0, g, tg, accq);

        __syncthreads();
        load_w128(Wk, Bs, tid);
        __syncthreads();
        zero_acc(acck);
        mma_chunk(As, Bs, R0, C0, g, tg, acck);

        score_ep(accq, acck, bq, bk, sdst, swap, rowbase, R0, C0, g, tg);

        __syncthreads();
        load_w128(Wv, Bs, tid);
        __syncthreads();
        zero_acc(accq);
        mma_chunk(As, Bs, R0, C0, g, tg, accq);
        v_ep(accq, bv, vdst, rowbase, R0, C0, g, tg);
    }
}

// ---------------- generic tf32 GEMM: C[M,N] = A@B (+A2@B2) + biases (+resid) (relu) ----------------
__global__ void __launch_bounds__(256) gemm_tf32_kernel(
    const float* __restrict__ A,  const float* __restrict__ Bw,
    const float* __restrict__ A2, const float* __restrict__ B2w,
    const float* __restrict__ bias, const float* __restrict__ bias2,
    const float* __restrict__ resid, float* __restrict__ C,
    int N, int K1, int K2, int relu)
{
    extern __shared__ float sm[];
    float* As = sm;
    float* Bs = sm + 64 * A_STRIDE;
    int tid = threadIdx.x;
    int lane = tid & 31, wid = tid >> 5;
    int g = lane >> 2, tg = lane & 3;
    int R0 = (wid >> 2) * 32, C0 = (wid & 3) * 32;
    int rowbase = blockIdx.x * 64;
    int colbase = blockIdx.y * 128;

    float acc[2][4][4];
    zero_acc(acc);

    int nc1 = K1 >> 7;
    int nc2 = A2 ? (K2 >> 7) : 0;
    for (int c = 0; c < nc1 + nc2; c++) {
        const float* Ap; const float* Bp; int lda, kb;
        if (c < nc1) { Ap = A;  Bp = Bw;  lda = K1; kb = c << 7; }
        else         { Ap = A2; Bp = B2w; lda = K2; kb = (c - nc1) << 7; }
        if (c) __syncthreads();
#pragma unroll
        for (int it = 0; it < 8; it++) {            // A chunk 64x128
            int idx = tid + it * 256;
            int r = idx >> 5, c4 = idx & 31;
            float4 v = *(const float4*)&Ap[(long)(rowbase + r) * lda + kb + c4 * 4];
            float4 h;
            h.x = cvt1(v.x); h.y = cvt1(v.y); h.z = cvt1(v.z); h.w = cvt1(v.w);
            *(float4*)&As[r * A_STRIDE + c4 * 4] = h;
        }
#pragma unroll
        for (int it = 0; it < 16; it++) {           // B chunk 128x128
            int idx = tid + it * 256;
            int r = idx >> 5, c4 = idx & 31;
            float4 v = *(const float4*)&Bp[(long)(kb + r) * N + colbase + c4 * 4];
            float4 h;
            h.x = cvt1(v.x); h.y = cvt1(v.y); h.z = cvt1(v.z); h.w = cvt1(v.w);
            *(float4*)&Bs[r * A_STRIDE + c4 * 4] = h;
        }
        __syncthreads();
        mma_chunk(As, Bs, R0, C0, g, tg, acc);
    }

#pragma unroll
    for (int i = 0; i < 2; i++)
#pragma unroll
        for (int j = 0; j < 4; j++) {
            int cg_ = colbase + C0 + 8 * j + 2 * tg;
            float b0 = 0.f, b1 = 0.f;
            if (bias)  { b0 += bias[cg_];  b1 += bias[cg_ + 1]; }
            if (bias2) { b0 += bias2[cg_]; b1 += bias2[cg_ + 1]; }
            long r0 = rowbase + R0 + 16 * i + g;
            long r1 = r0 + 8;
            float v00 = acc[i][j][0] + b0, v01 = acc[i][j][1] + b1;
            float v10 = acc[i][j][2] + b0, v11 = acc[i][j][3] + b1;
            if (resid) {
                float2 q0 = *(const float2*)&resid[r0 * N + cg_];
                float2 q1 = *(const float2*)&resid[r1 * N + cg_];
                v00 += q0.x; v01 += q0.y; v10 += q1.x; v11 += q1.y;
            }
            if (relu) {
                v00 = fmaxf(v00, 0.f); v01 = fmaxf(v01, 0.f);
                v10 = fmaxf(v10, 0.f); v11 = fmaxf(v11, 0.f);
            }
            *(float2*)&C[r0 * N + cg_] = make_float2(v00, v01);
            *(float2*)&C[r1 * N + cg_] = make_float2(v10, v11);
        }
}

// ---------------- LN kernel: warp per 128-wide row ----------------
__global__ void __launch_bounds__(256) ln_kernel(const float* __restrict__ in,
                                                 const float* __restrict__ gam,
                                                 const float* __restrict__ bet,
                                                 float* __restrict__ out) {
    int w = blockIdx.x * 8 + (threadIdx.x >> 5);
    int lane = threadIdx.x & 31;
    float4 v = ((const float4*)(in + (long)w * DD))[lane];
    float s = v.x + v.y + v.z + v.w;
#pragma unroll
    for (int o = 16; o > 0; o >>= 1) s += __shfl_xor_sync(0xffffffffu, s, o);
    float mean = s * (1.f / 128.f);
    float4 d = make_float4(v.x - mean, v.y - mean, v.z - mean, v.w - mean);
    float q = d.x * d.x + d.y * d.y + d.z * d.z + d.w * d.w;
#pragma unroll
    for (int o = 16; o > 0; o >>= 1) q += __shfl_xor_sync(0xffffffffu, q, o);
    float r = rsqrtf(q * (1.f / 128.f) + 1e-5f);
    float4 gg = ((const float4*)gam)[lane];
    float4 bb = ((const float4*)bet)[lane];
    float4 o4;
    o4.x = d.x * r * gg.x + bb.x;
    o4.y = d.y * r * gg.y + bb.y;
    o4.z = d.z * r * gg.z + bb.z;
    o4.w = d.w * r * gg.w + bb.w;
    ((float4*)(out + (long)w * DD))[lane] = o4;
}

// ---------------- softmax: warp per contiguous 160-float row ----------------
__global__ void __launch_bounds__(256) softmax_kernel() {
    int w = blockIdx.x * 8 + (threadIdx.x >> 5);
    int lane = threadIdx.x & 31;
    const int HALF = BB * NN * HH;   // 10240
    float* p = (w < HALF) ? (g_s_in + (long)w * NN)
                          : (g_s_out + (long)(w - HALF) * NN);
    float v[5];
#pragma unroll
    for (int t = 0; t < 5; t++) v[t] = p[lane + 32 * t];
    float mx = v[0];
#pragma unroll
    for (int t = 1; t < 5; t++) mx = fmaxf(mx, v[t]);
#pragma unroll
    for (int o = 16; o > 0; o >>= 1) mx = fmaxf(mx, __shfl_xor_sync(0xffffffffu, mx, o));
    float sum = 0.f;
#pragma unroll
    for (int t = 0; t < 5; t++) { v[t] = __expf(v[t] - mx); sum += v[t]; }
#pragma unroll
    for (int o = 16; o > 0; o >>= 1) sum += __shfl_xor_sync(0xffffffffu, sum, o);
    float inv = __frcp_rn(sum);
#pragma unroll
    for (int t = 0; t < 5; t++) p[lane + 32 * t] = v[t] * inv;
}

// ---------------- attention-weighted reductions ----------------
__global__ void __launch_bounds__(128) attn_reduce_kernel() {
    __shared__ float a_s[HH * NN];     // 1280
    int e = threadIdx.x;
    int bn = blockIdx.x;
    int b = bn / NN, n = bn % NN;
    const float* s = (blockIdx.y == 0) ? g_s_in : g_s_out;
    long abase = (long)(b * NN + n) * HH * NN;
    for (int idx = e; idx < HH * NN; idx += 128) a_s[idx] = s[abase + idx];
    __syncthreads();
    int h = e >> 4;
    float acc = 0.f;
    if (blockIdx.y == 0) {
        long vbase = ((long)(b * NN) * NN + n) * DD + e;   // + i*NN*DD
#pragma unroll 4
        for (int i = 0; i < NN; i++)
            acc += a_s[h * NN + i] * g_v_in[vbase + (long)i * NN * DD];
        g_out_in[(long)bn * DD + e] = acc;
    } else {
        long vbase = (long)(b * NN + n) * NN * DD + e;     // + j*DD
#pragma unroll 4
        for (int j = 0; j < NN; j++)
            acc += a_s[h * NN + j] * g_v_out[vbase + (long)j * DD];
        g_out_out[(long)bn * DD + e] = acc;
    }
}

// ---------------- edge_out broadcast ----------------
__global__ void edge_out_kernel(const float* __restrict__ b_edge, float* __restrict__ dst) {
    long gid = (long)blockIdx.x * blockDim.x + threadIdx.x;   // per float4
    int e4 = (int)(gid & 31);
    long rem = gid >> 5;
    int j = (int)(rem % NN);
    long rem2 = rem / NN;
    int i = (int)(rem2 % NN);
    int b = (int)(rem2 / NN);
    float4 xi = ((const float4*)g_xi)[(b * NN + i) * 32 + e4];
    float4 xj = ((const float4*)g_xj)[(b * NN + j) * 32 + e4];
    float4 be = ((const float4*)b_edge)[e4];
    float4 o;
    o.x = xi.x + xj.x + be.x;
    o.y = xi.y + xj.y + be.y;
    o.z = xi.z + xj.z + be.z;
    o.w = xi.w + xj.w + be.w;
    ((float4*)dst)[gid] = o;
}

// ---------------- launch ----------------
extern "C" void kernel_launch(void* const* d_in, const int* in_sizes, int n_in,
                              void* d_out, int out_size) {
    const float* node   = (const float*)d_in[0];
    const float* edge   = (const float*)d_in[1];
    const float* Wqi = (const float*)d_in[2];  const float* bqi = (const float*)d_in[3];
    const float* Wki = (const float*)d_in[4];  const float* bki = (const float*)d_in[5];
    const float* Wvi = (const float*)d_in[6];  const float* bvi = (const float*)d_in[7];
    const float* Wqo = (const float*)d_in[8];  const float* bqo = (const float*)d_in[9];
    const float* Wko = (const float*)d_in[10]; const float* bko = (const float*)d_in[11];
    const float* Wvo = (const float*)d_in[12]; const float* bvo = (const float*)d_in[13];
    const float* Wpi = (const float*)d_in[14]; const float* bpi = (const float*)d_in[15];
    const float* Wpo = (const float*)d_in[16]; const float* bpo = (const float*)d_in[17];
    const float* Wf1 = (const float*)d_in[18]; const float* bf1 = (const float*)d_in[19];
    const float* Wf2 = (const float*)d_in[20]; const float* bf2 = (const float*)d_in[21];
    const float* g1  = (const float*)d_in[22]; const float* be1 = (const float*)d_in[23];
    const float* g2  = (const float*)d_in[24]; const float* be2 = (const float*)d_in[25];
    const float* Wedge = (const float*)d_in[26];
    const float* bedge = (const float*)d_in[27];
    float* out = (float*)d_out;

    float* g_tmp1_p; cudaGetSymbolAddress((void**)&g_tmp1_p, g_tmp1);
    float* g_x1_p;   cudaGetSymbolAddress((void**)&g_x1_p, g_x1);
    float* g_ff_p;   cudaGetSymbolAddress((void**)&g_ff_p, g_ff);
    float* g_oi_p;   cudaGetSymbolAddress((void**)&g_oi_p, g_out_in);
    float* g_oo_p;   cudaGetSymbolAddress((void**)&g_oo_p, g_out_out);
    float* g_xi_p;   cudaGetSymbolAddress((void**)&g_xi_p, g_xi);
    float* g_xj_p;   cudaGetSymbolAddress((void**)&g_xj_p, g_xj);

    size_t smem = SMEM_FLOATS * sizeof(float);   // 101376 B
    cudaFuncSetAttribute(fused_edge_kernel,
                         cudaFuncAttributeMaxDynamicSharedMemorySize, (int)smem);
    cudaFuncSetAttribute(gemm_tf32_kernel,
                         cudaFuncAttributeMaxDynamicSharedMemorySize, (int)smem);

    // 1) edge projections + scores + v
    fused_edge_kernel<<<ROWS_TOTAL / 64, 256, smem>>>(
        edge, Wqi, bqi, Wki, bki, Wvi, bvi, Wqo, bqo, Wko, bko, Wvo, bvo);

    // 2) softmax (rows contiguous)
    softmax_kernel<<<(2 * BB * NN * HH) / 8, 256>>>();

    // 3) attention reductions
    attn_reduce_kernel<<<dim3(BB * NN, 2), 128>>>();

    // 4) t = out_in@Wpi + out_out@Wpo + bpi + bpo + node
    gemm_tf32_kernel<<<dim3(BB * NN / 64, 1), 256, smem>>>(
        g_oi_p, Wpi, g_oo_p, Wpo, bpi, bpo, node, g_tmp1_p, 128, 128, 128, 0);
    // 5) x1 = LN(t)
    ln_kernel<<<BB * NN / 8, 256>>>(g_tmp1_p, g1, be1, g_x1_p);
    // 6) ff = relu(x1@Wf1 + bf1)
    gemm_tf32_kernel<<<dim3(BB * NN / 64, 4), 256, smem>>>(
        g_x1_p, Wf1, nullptr, nullptr, bf1, nullptr, nullptr, g_ff_p, 512, 128, 0, 1);
    // 7) t2 = ff@Wf2 + bf2 + x1
    gemm_tf32_kernel<<<dim3(BB * NN / 64, 1), 256, smem>>>(
        g_ff_p, Wf2, nullptr, nullptr, bf2, nullptr, g_x1_p, g_tmp1_p, 128, 512, 0, 0);
    // 8) x2 = LN(t2) -> output x region
    ln_kernel<<<BB * NN / 8, 256>>>(g_tmp1_p, g2, be2, out);
    // 9) xi = x2@Wi ; xj = x2@Wj
    gemm_tf32_kernel<<<dim3(BB * NN / 64, 1), 256, smem>>>(
        out, Wedge, nullptr, nullptr, nullptr, nullptr, nullptr, g_xi_p, 128, 128, 0, 0);
    gemm_tf32_kernel<<<dim3(BB * NN / 64, 1), 256, smem>>>(
        out, Wedge + 128 * 128, nullptr, nullptr, nullptr, nullptr, nullptr, g_xj_p, 128, 128, 0, 0);

    // 10) edge_out broadcast
    edge_out_kernel<<<(BB * NN * NN * DD / 4) / 256, 256>>>(bedge, out + BB * NN * DD);
}

// round 5
// speedup vs baseline: 18.4783x; 1.0722x over previous
#include <cuda_runtime.h>
#include <cstdint>

#define BB 8
#define NN 160
#define DD 128
#define HH 8
#define ROWS_TOTAL (BB*NN*NN)   // 204800

// ---------------- scratch ----------------
__device__ float g_s_in [ROWS_TOTAL*HH];     // [b, j, h, i] contiguous in i
__device__ float g_s_out[ROWS_TOTAL*HH];     // [b, i, h, j] contiguous in j
__device__ float g_v_in [ROWS_TOTAL*DD];
__device__ float g_v_out[ROWS_TOTAL*DD];
__device__ float g_out_in [BB*NN*DD];
__device__ float g_out_out[BB*NN*DD];
__device__ float g_x1  [BB*NN*DD];
__device__ float g_ff  [BB*NN*512];
__device__ float g_xi[BB*NN*DD];
__device__ float g_xj[BB*NN*DD];

// ---------------- tf32 helpers ----------------
__device__ __forceinline__ float cvt1(float x) {
    uint32_t u; asm("cvt.rna.tf32.f32 %0, %1;" : "=r"(u) : "f"(x));
    return __uint_as_float(u);
}

#define MMA_TF32(d, a, b)                                                   \
    asm("mma.sync.aligned.m16n8k8.row.col.f32.tf32.tf32.f32 "               \
        "{%0,%1,%2,%3}, {%4,%5,%6,%7}, {%8,%9}, {%0,%1,%2,%3};"             \
        : "+f"(d[0]), "+f"(d[1]), "+f"(d[2]), "+f"(d[3])                    \
        : "r"(a[0]), "r"(a[1]), "r"(a[2]), "r"(a[3]), "r"(b[0]), "r"(b[1]))

#define A_STRIDE 132

// =======================================================================
//  FUSED EDGE KERNEL: 128-row blocks, 8 warps (4x2), 32x64 warp tiles,
//  cp.async double-buffered weights
// =======================================================================
// smem: As[128*132] | W0[128*132] | W1[128*132]  = 202752 bytes
#define ESM_A   0
#define ESM_W0  (128*A_STRIDE)
#define ESM_W1  (2*128*A_STRIDE)
#define ESM_TOTAL (3*128*A_STRIDE)

__device__ __forceinline__ void prefetch_w(const float* __restrict__ W,
                                           float* buf, int tid) {
#pragma unroll
    for (int it = 0; it < 16; it++) {
        int idx = tid + it * 256;       // 4096 float4
        int r = idx >> 5, c4 = idx & 31;
        uint32_t dst = (uint32_t)__cvta_generic_to_shared(&buf[r * A_STRIDE + c4 * 4]);
        const float* src = W + r * 128 + c4 * 4;
        asm volatile("cp.async.cg.shared.global [%0], [%1], 16;" :: "r"(dst), "l"(src));
    }
    asm volatile("cp.async.commit_group;");
}
__device__ __forceinline__ void wait_cp() {
    asm volatile("cp.async.wait_group 0;" ::: "memory");
}

__device__ __forceinline__ void zero64(float (&acc)[2][8][4]) {
#pragma unroll
    for (int i = 0; i < 2; i++)
#pragma unroll
        for (int j = 0; j < 8; j++)
#pragma unroll
            for (int t = 0; t < 4; t++) acc[i][j][t] = 0.f;
}

__device__ __forceinline__ void mma_pass64(const float* As, const float* Ws,
                                           int R0, int C0, int g, int tg,
                                           float (&acc)[2][8][4]) {
#pragma unroll 2
    for (int ks = 0; ks < 16; ks++) {
        int k0 = ks * 8;
        uint32_t a[2][4];
#pragma unroll
        for (int i = 0; i < 2; i++) {
            int r0 = (R0 + 16 * i + g) * A_STRIDE + k0 + tg;
            int r1 = r0 + 8 * A_STRIDE;
            a[i][0] = __float_as_uint(As[r0]);
            a[i][1] = __float_as_uint(As[r1]);
            a[i][2] = __float_as_uint(As[r0 + 4]);
            a[i][3] = __float_as_uint(As[r1 + 4]);
        }
        uint32_t b[8][2];
#pragma unroll
        for (int j = 0; j < 8; j++) {
            int cb = C0 + 8 * j + g;
            b[j][0] = __float_as_uint(Ws[(k0 + tg) * A_STRIDE + cb]);
            b[j][1] = __float_as_uint(Ws[(k0 + tg + 4) * A_STRIDE + cb]);
        }
#pragma unroll
        for (int i = 0; i < 2; i++)
#pragma unroll
            for (int j = 0; j < 8; j++)
                MMA_TF32(acc[i][j], a[i], b[j]);
    }
}

// frag C map: c0:(g,2tg) c1:(g,2tg+1) c2:(g+8,2tg) c3:(g+8,2tg+1) rel (R0+16i, C0+8j)
__device__ __forceinline__ void score_ep64(const float (&aq)[2][8][4],
                                           const float (&ak)[2][8][4],
                                           const float* __restrict__ bq,
                                           const float* __restrict__ bk,
                                           float* __restrict__ sdst, int swap,
                                           int rowbase, int R0, int C0,
                                           int g, int tg) {
    float p[2][2][4];
#pragma unroll
    for (int i = 0; i < 2; i++)
#pragma unroll
        for (int hf = 0; hf < 2; hf++)
#pragma unroll
            for (int hh = 0; hh < 4; hh++) p[i][hf][hh] = 0.f;

#pragma unroll
    for (int i = 0; i < 2; i++)
#pragma unroll
        for (int j = 0; j < 8; j++) {
            int c = C0 + 8 * j + 2 * tg;
            float bq0 = bq[c], bq1 = bq[c + 1];
            float bk0 = bk[c], bk1 = bk[c + 1];
            int hh = j >> 1;
            float q0 = aq[i][j][0] + bq0, q1 = aq[i][j][1] + bq1;
            float k0 = ak[i][j][0] + bk0, k1 = ak[i][j][1] + bk1;
            p[i][0][hh] += q0 * k0 + q1 * k1;
            q0 = aq[i][j][2] + bq0; q1 = aq[i][j][3] + bq1;
            k0 = ak[i][j][2] + bk0; k1 = ak[i][j][3] + bk1;
            p[i][1][hh] += q0 * k0 + q1 * k1;
        }
#pragma unroll
    for (int i = 0; i < 2; i++)
#pragma unroll
        for (int hf = 0; hf < 2; hf++)
#pragma unroll
            for (int hh = 0; hh < 4; hh++) {
                float v = p[i][hf][hh];
                v += __shfl_xor_sync(0xffffffffu, v, 1);
                v += __shfl_xor_sync(0xffffffffu, v, 2);
                p[i][hf][hh] = v;
            }
    if (tg == 0) {
#pragma unroll
        for (int i = 0; i < 2; i++)
#pragma unroll
            for (int hf = 0; hf < 2; hf++)
#pragma unroll
                for (int hh = 0; hh < 4; hh++) {
                    int grow = rowbase + R0 + 16 * i + 8 * hf + g;
                    int b = grow / (NN * NN);
                    int rem = grow - b * NN * NN;
                    int ii = rem / NN;
                    int jj = rem - ii * NN;
                    int h = (C0 >> 4) + hh;
                    int r1 = swap ? jj : ii;
                    int r2 = swap ? ii : jj;
                    sdst[((b * NN + r1) * HH + h) * NN + r2] = p[i][hf][hh] * 0.25f;
                }
    }
}

__device__ __forceinline__ void v_ep64(const float (&acc)[2][8][4],
                                       const float* __restrict__ bv,
                                       float* __restrict__ vdst,
                                       int rowbase, int R0, int C0,
                                       int g, int tg) {
#pragma unroll
    for (int i = 0; i < 2; i++)
#pragma unroll
        for (int j = 0; j < 8; j++) {
            int c = C0 + 8 * j + 2 * tg;
            float bv0 = bv[c], bv1 = bv[c + 1];
            long r0 = rowbase + R0 + 16 * i + g;
            long r1 = r0 + 8;
            *(float2*)&vdst[r0 * DD + c] = make_float2(acc[i][j][0] + bv0, acc[i][j][1] + bv1);
            *(float2*)&vdst[r1 * DD + c] = make_float2(acc[i][j][2] + bv0, acc[i][j][3] + bv1);
        }
}

__global__ void __launch_bounds__(256, 1) fused_edge_kernel(
    const float* __restrict__ edge,
    const float* __restrict__ Wqi, const float* __restrict__ bqi,
    const float* __restrict__ Wki, const float* __restrict__ bki,
    const float* __restrict__ Wvi, const float* __restrict__ bvi,
    const float* __restrict__ Wqo, const float* __restrict__ bqo,
    const float* __restrict__ Wko, const float* __restrict__ bko,
    const float* __restrict__ Wvo, const float* __restrict__ bvo)
{
    extern __shared__ float sm[];
    float* As = sm + ESM_A;
    float* W0 = sm + ESM_W0;
    float* W1 = sm + ESM_W1;
    int tid = threadIdx.x;
    int lane = tid & 31, wid = tid >> 5;
    int g = lane >> 2, tg = lane & 3;
    int R0 = (wid >> 1) * 32;     // 4 row bands of 32
    int C0 = (wid & 1) * 64;      // 2 col bands of 64
    int rowbase = blockIdx.x * 128;

    // start W0 prefetch, then load + convert E tile (128 x 128)
    prefetch_w(Wqi, W0, tid);
    const float4* Eg = (const float4*)(edge + (long)rowbase * DD);
#pragma unroll
    for (int it = 0; it < 16; it++) {
        int idx = tid + it * 256;     // 4096 float4
        int r = idx >> 5, c4 = idx & 31;
        float4 v = Eg[idx];
        float4 h;
        h.x = cvt1(v.x); h.y = cvt1(v.y); h.z = cvt1(v.z); h.w = cvt1(v.w);
        *(float4*)&As[r * A_STRIDE + c4 * 4] = h;
    }

    float accQ[2][8][4], accB[2][8][4];

    // pass 0: q_in
    wait_cp(); __syncthreads();
    prefetch_w(Wki, W1, tid);
    zero64(accQ);
    mma_pass64(As, W0, R0, C0, g, tg, accQ);

    // pass 1: k_in -> scores(in)
    wait_cp(); __syncthreads();
    prefetch_w(Wvi, W0, tid);
    zero64(accB);
    mma_pass64(As, W1, R0, C0, g, tg, accB);
    score_ep64(accQ, accB, bqi, bki, g_s_in, 1, rowbase, R0, C0, g, tg);

    // pass 2: v_in
    wait_cp(); __syncthreads();
    prefetch_w(Wqo, W1, tid);
    zero64(accB);
    mma_pass64(As, W0, R0, C0, g, tg, accB);
    v_ep64(accB, bvi, g_v_in, rowbase, R0, C0, g, tg);

    // pass 3: q_out
    wait_cp(); __syncthreads();
    prefetch_w(Wko, W0, tid);
    zero64(accQ);
    mma_pass64(As, W1, R0, C0, g, tg, accQ);

    // pass 4: k_out -> scores(out)
    wait_cp(); __syncthreads();
    prefetch_w(Wvo, W1, tid);
    zero64(accB);
    mma_pass64(As, W0, R0, C0, g, tg, accB);
    score_ep64(accQ, accB, bqo, bko, g_s_out, 0, rowbase, R0, C0, g, tg);

    // pass 5: v_out
    wait_cp(); __syncthreads();
    zero64(accB);
    mma_pass64(As, W1, R0, C0, g, tg, accB);
    v_ep64(accB, bvo, g_v_out, rowbase, R0, C0, g, tg);
}

// =======================================================================
//  generic tf32 GEMM (64x128 block tile, 8 warps, 32x32 warp tiles)
//  optional: dual-A, bias2, resid, relu, LN epilogue, dual-output select
// =======================================================================
#define GSM_A 0
#define GSM_B (64*A_STRIDE)
#define GSM_C (64*A_STRIDE + 128*A_STRIDE)
#define GSM_TOTAL (64*A_STRIDE + 128*A_STRIDE + 64*A_STRIDE)

__device__ __forceinline__ void zero32(float (&acc)[2][4][4]) {
#pragma unroll
    for (int i = 0; i < 2; i++)
#pragma unroll
        for (int j = 0; j < 4; j++)
#pragma unroll
            for (int t = 0; t < 4; t++) acc[i][j][t] = 0.f;
}

__device__ __forceinline__ void mma_pass32(const float* As, const float* Bs,
                                           int R0, int C0, int g, int tg,
                                           float (&acc)[2][4][4]) {
#pragma unroll 4
    for (int ks = 0; ks < 16; ks++) {
        int k0 = ks * 8;
        uint32_t a[2][4];
#pragma unroll
        for (int i = 0; i < 2; i++) {
            int r0 = (R0 + 16 * i + g) * A_STRIDE + k0 + tg;
            int r1 = r0 + 8 * A_STRIDE;
            a[i][0] = __float_as_uint(As[r0]);
            a[i][1] = __float_as_uint(As[r1]);
            a[i][2] = __float_as_uint(As[r0 + 4]);
            a[i][3] = __float_as_uint(As[r1 + 4]);
        }
        uint32_t b[4][2];
#pragma unroll
        for (int j = 0; j < 4; j++) {
            int cb = C0 + 8 * j + g;
            b[j][0] = __float_as_uint(Bs[(k0 + tg) * A_STRIDE + cb]);
            b[j][1] = __float_as_uint(Bs[(k0 + tg + 4) * A_STRIDE + cb]);
        }
#pragma unroll
        for (int i = 0; i < 2; i++)
#pragma unroll
            for (int j = 0; j < 4; j++)
                MMA_TF32(acc[i][j], a[i], b[j]);
    }
}

__global__ void __launch_bounds__(256) gemm_tf32_kernel(
    const float* __restrict__ A,  const float* __restrict__ Bw,
    const float* __restrict__ A2, const float* __restrict__ B2w,
    const float* __restrict__ bias, const float* __restrict__ bias2,
    const float* __restrict__ resid, float* __restrict__ C, float* __restrict__ C2,
    const float* __restrict__ gam, const float* __restrict__ bet,
    int N, int K1, int K2, int relu, int dualout)
{
    extern __shared__ float sm[];
    float* As = sm + GSM_A;
    float* Bs = sm + GSM_B;
    float* Cs = sm + GSM_C;
    int tid = threadIdx.x;
    int lane = tid & 31, wid = tid >> 5;
    int g = lane >> 2, tg = lane & 3;
    int R0 = (wid >> 2) * 32, C0 = (wid & 3) * 32;
    int rowbase = blockIdx.x * 64;
    int colbase = dualout ? 0 : blockIdx.y * 128;
    const float* Bsel = (dualout && blockIdx.y == 1) ? B2w : Bw;
    float* Csel = (dualout && blockIdx.y == 1) ? C2 : C;
    const float* B2sel = dualout ? nullptr : B2w;

    float acc[2][4][4];
    zero32(acc);

    int nc1 = K1 >> 7;
    int nc2 = (A2 && !dualout) ? (K2 >> 7) : 0;
    for (int c = 0; c < nc1 + nc2; c++) {
        const float* Ap; const float* Bp; int lda, kb;
        if (c < nc1) { Ap = A;  Bp = Bsel;  lda = K1; kb = c << 7; }
        else         { Ap = A2; Bp = B2sel; lda = K2; kb = (c - nc1) << 7; }
        if (c) __syncthreads();
#pragma unroll
        for (int it = 0; it < 8; it++) {
            int idx = tid + it * 256;
            int r = idx >> 5, c4 = idx & 31;
            float4 v = *(const float4*)&Ap[(long)(rowbase + r) * lda + kb + c4 * 4];
            float4 h;
            h.x = cvt1(v.x); h.y = cvt1(v.y); h.z = cvt1(v.z); h.w = cvt1(v.w);
            *(float4*)&As[r * A_STRIDE + c4 * 4] = h;
        }
#pragma unroll
        for (int it = 0; it < 16; it++) {
            int idx = tid + it * 256;
            int r = idx >> 5, c4 = idx & 31;
            float4 v = *(const float4*)&Bp[(long)(kb + r) * N + colbase + c4 * 4];
            float4 h;
            h.x = cvt1(v.x); h.y = cvt1(v.y); h.z = cvt1(v.z); h.w = cvt1(v.w);
            *(float4*)&Bs[r * A_STRIDE + c4 * 4] = h;
        }
        __syncthreads();
        mma_pass32(As, Bs, R0, C0, g, tg, acc);
    }

    // epilogue: bias / resid / relu; either direct store or LN via smem
#pragma unroll
    for (int i = 0; i < 2; i++)
#pragma unroll
        for (int j = 0; j < 4; j++) {
            int cl = C0 + 8 * j + 2 * tg;
            int cg_ = colbase + cl;
            float b0 = 0.f, b1 = 0.f;
            if (bias)  { b0 += bias[cg_];  b1 += bias[cg_ + 1]; }
            if (bias2) { b0 += bias2[cg_]; b1 += bias2[cg_ + 1]; }
            long r0 = rowbase + R0 + 16 * i + g;
            long r1 = r0 + 8;
            float v00 = acc[i][j][0] + b0, v01 = acc[i][j][1] + b1;
            float v10 = acc[i][j][2] + b0, v11 = acc[i][j][3] + b1;
            if (resid) {
                float2 q0 = *(const float2*)&resid[r0 * N + cg_];
                float2 q1 = *(const float2*)&resid[r1 * N + cg_];
                v00 += q0.x; v01 += q0.y; v10 += q1.x; v11 += q1.y;
            }
            if (relu) {
                v00 = fmaxf(v00, 0.f); v01 = fmaxf(v01, 0.f);
                v10 = fmaxf(v10, 0.f); v11 = fmaxf(v11, 0.f);
            }
            if (gam) {
                int lr0 = R0 + 16 * i + g, lr1 = lr0 + 8;
                *(float2*)&Cs[lr0 * A_STRIDE + cl] = make_float2(v00, v01);
                *(float2*)&Cs[lr1 * A_STRIDE + cl] = make_float2(v10, v11);
            } else {
                *(float2*)&Csel[r0 * N + cg_] = make_float2(v00, v01);
                *(float2*)&Csel[r1 * N + cg_] = make_float2(v10, v11);
            }
        }

    if (gam) {
        __syncthreads();
        // LN: warp wid handles rows wid*8 .. wid*8+7 (N must be 128)
#pragma unroll
        for (int r = 0; r < 8; r++) {
            int row = wid * 8 + r;
            float4 v = *(const float4*)&Cs[row * A_STRIDE + lane * 4];
            float s = v.x + v.y + v.z + v.w;
#pragma unroll
            for (int o = 16; o > 0; o >>= 1) s += __shfl_xor_sync(0xffffffffu, s, o);
            float mean = s * (1.f / 128.f);
            float4 dd = make_float4(v.x - mean, v.y - mean, v.z - mean, v.w - mean);
            float q = dd.x * dd.x + dd.y * dd.y + dd.z * dd.z + dd.w * dd.w;
#pragma unroll
            for (int o = 16; o > 0; o >>= 1) q += __shfl_xor_sync(0xffffffffu, q, o);
            float rs = rsqrtf(q * (1.f / 128.f) + 1e-5f);
            float4 gg = ((const float4*)gam)[lane];
            float4 bb = ((const float4*)bet)[lane];
            float4 o4;
            o4.x = dd.x * rs * gg.x + bb.x;
            o4.y = dd.y * rs * gg.y + bb.y;
            o4.z = dd.z * rs * gg.z + bb.z;
            o4.w = dd.w * rs * gg.w + bb.w;
            *(float4*)&C[((long)rowbase + row) * 128 + lane * 4] = o4;
        }
    }
}

// ---------------- softmax: warp per contiguous 160-float row ----------------
__global__ void __launch_bounds__(256) softmax_kernel() {
    int w = blockIdx.x * 8 + (threadIdx.x >> 5);
    int lane = threadIdx.x & 31;
    const int HALF = BB * NN * HH;   // 10240
    float* p = (w < HALF) ? (g_s_in + (long)w * NN)
                          : (g_s_out + (long)(w - HALF) * NN);
    float v[5];
#pragma unroll
    for (int t = 0; t < 5; t++) v[t] = p[lane + 32 * t];
    float mx = v[0];
#pragma unroll
    for (int t = 1; t < 5; t++) mx = fmaxf(mx, v[t]);
#pragma unroll
    for (int o = 16; o > 0; o >>= 1) mx = fmaxf(mx, __shfl_xor_sync(0xffffffffu, mx, o));
    float sum = 0.f;
#pragma unroll
    for (int t = 0; t < 5; t++) { v[t] = __expf(v[t] - mx); sum += v[t]; }
#pragma unroll
    for (int o = 16; o > 0; o >>= 1) sum += __shfl_xor_sync(0xffffffffu, sum, o);
    float inv = __frcp_rn(sum);
#pragma unroll
    for (int t = 0; t < 5; t++) p[lane + 32 * t] = v[t] * inv;
}

// ---------------- attention-weighted reductions ----------------
__global__ void __launch_bounds__(128) attn_reduce_kernel() {
    __shared__ float a_s[HH * NN];     // 1280
    int e = threadIdx.x;
    int bn = blockIdx.x;
    int b = bn / NN, n = bn % NN;
    const float* s = (blockIdx.y == 0) ? g_s_in : g_s_out;
    long abase = (long)(b * NN + n) * HH * NN;
    for (int idx = e; idx < HH * NN; idx += 128) a_s[idx] = s[abase + idx];
    __syncthreads();
    int h = e >> 4;
    float acc = 0.f;
    if (blockIdx.y == 0) {
        long vbase = ((long)(b * NN) * NN + n) * DD + e;
#pragma unroll 4
        for (int i = 0; i < NN; i++)
            acc += a_s[h * NN + i] * g_v_in[vbase + (long)i * NN * DD];
        g_out_in[(long)bn * DD + e] = acc;
    } else {
        long vbase = (long)(b * NN + n) * NN * DD + e;
#pragma unroll 4
        for (int j = 0; j < NN; j++)
            acc += a_s[h * NN + j] * g_v_out[vbase + (long)j * DD];
        g_out_out[(long)bn * DD + e] = acc;
    }
}

// ---------------- edge_out broadcast ----------------
__global__ void edge_out_kernel(const float* __restrict__ b_edge, float* __restrict__ dst) {
    long gid = (long)blockIdx.x * blockDim.x + threadIdx.x;
    int e4 = (int)(gid & 31);
    long rem = gid >> 5;
    int j = (int)(rem % NN);
    long rem2 = rem / NN;
    int i = (int)(rem2 % NN);
    int b = (int)(rem2 / NN);
    float4 xi = ((const float4*)g_xi)[(b * NN + i) * 32 + e4];
    float4 xj = ((const float4*)g_xj)[(b * NN + j) * 32 + e4];
    float4 be = ((const float4*)b_edge)[e4];
    float4 o;
    o.x = xi.x + xj.x + be.x;
    o.y = xi.y + xj.y + be.y;
    o.z = xi.z + xj.z + be.z;
    o.w = xi.w + xj.w + be.w;
    ((float4*)dst)[gid] = o;
}

// ---------------- launch ----------------
extern "C" void kernel_launch(void* const* d_in, const int* in_sizes, int n_in,
                              void* d_out, int out_size) {
    const float* node   = (const float*)d_in[0];
    const float* edge   = (const float*)d_in[1];
    const float* Wqi = (const float*)d_in[2];  const float* bqi = (const float*)d_in[3];
    const float* Wki = (const float*)d_in[4];  const float* bki = (const float*)d_in[5];
    const float* Wvi = (const float*)d_in[6];  const float* bvi = (const float*)d_in[7];
    const float* Wqo = (const float*)d_in[8];  const float* bqo = (const float*)d_in[9];
    const float* Wko = (const float*)d_in[10]; const float* bko = (const float*)d_in[11];
    const float* Wvo = (const float*)d_in[12]; const float* bvo = (const float*)d_in[13];
    const float* Wpi = (const float*)d_in[14]; const float* bpi = (const float*)d_in[15];
    const float* Wpo = (const float*)d_in[16]; const float* bpo = (const float*)d_in[17];
    const float* Wf1 = (const float*)d_in[18]; const float* bf1 = (const float*)d_in[19];
    const float* Wf2 = (const float*)d_in[20]; const float* bf2 = (const float*)d_in[21];
    const float* g1  = (const float*)d_in[22]; const float* be1 = (const float*)d_in[23];
    const float* g2  = (const float*)d_in[24]; const float* be2 = (const float*)d_in[25];
    const float* Wedge = (const float*)d_in[26];
    const float* bedge = (const float*)d_in[27];
    float* out = (float*)d_out;

    float* g_x1_p;   cudaGetSymbolAddress((void**)&g_x1_p, g_x1);
    float* g_ff_p;   cudaGetSymbolAddress((void**)&g_ff_p, g_ff);
    float* g_oi_p;   cudaGetSymbolAddress((void**)&g_oi_p, g_out_in);
    float* g_oo_p;   cudaGetSymbolAddress((void**)&g_oo_p, g_out_out);
    float* g_xi_p;   cudaGetSymbolAddress((void**)&g_xi_p, g_xi);
    float* g_xj_p;   cudaGetSymbolAddress((void**)&g_xj_p, g_xj);

    size_t smemE = ESM_TOTAL * sizeof(float);   // 202752
    size_t smemG = GSM_TOTAL * sizeof(float);   // 135168
    cudaFuncSetAttribute(fused_edge_kernel,
                         cudaFuncAttributeMaxDynamicSharedMemorySize, (int)smemE);
    cudaFuncSetAttribute(gemm_tf32_kernel,
                         cudaFuncAttributeMaxDynamicSharedMemorySize, (int)smemG);

    // 1) edge projections + scores + v  (128-row tiles, cp.async W pipeline)
    fused_edge_kernel<<<ROWS_TOTAL / 128, 256, smemE>>>(
        edge, Wqi, bqi, Wki, bki, Wvi, bvi, Wqo, bqo, Wko, bko, Wvo, bvo);

    // 2) softmax
    softmax_kernel<<<(2 * BB * NN * HH) / 8, 256>>>();

    // 3) attention reductions
    attn_reduce_kernel<<<dim3(BB * NN, 2), 128>>>();

    // 4) x1 = LN(out_in@Wpi + out_out@Wpo + bpi + bpo + node)   [GEMM+LN fused]
    gemm_tf32_kernel<<<dim3(BB * NN / 64, 1), 256, smemG>>>(
        g_oi_p, Wpi, g_oo_p, Wpo, bpi, bpo, node, g_x1_p, nullptr,
        g1, be1, 128, 128, 128, 0, 0);

    // 5) ff = relu(x1@Wf1 + bf1)
    gemm_tf32_kernel<<<dim3(BB * NN / 64, 4), 256, smemG>>>(
        g_x1_p, Wf1, nullptr, nullptr, bf1, nullptr, nullptr, g_ff_p, nullptr,
        nullptr, nullptr, 512, 128, 0, 1, 0);

    // 6) x2 = LN(ff@Wf2 + bf2 + x1) -> out x region   [GEMM+LN fused]
    gemm_tf32_kernel<<<dim3(BB * NN / 64, 1), 256, smemG>>>(
        g_ff_p, Wf2, nullptr, nullptr, bf2, nullptr, g_x1_p, out, nullptr,
        g2, be2, 128, 512, 0, 0, 0);

    // 7) xi = x2@Wi ; xj = x2@Wj  (one launch, grid.y selects weight/dst)
    gemm_tf32_kernel<<<dim3(BB * NN / 64, 2), 256, smemG>>>(
        out, Wedge, nullptr, Wedge + 128 * 128, nullptr, nullptr, nullptr,
        g_xi_p, g_xj_p, nullptr, nullptr, 128, 128, 0, 0, 1);

    // 8) edge_out broadcast
    edge_out_kernel<<<(BB * NN * NN * DD / 4) / 256, 256>>>(bedge, out + BB * NN * DD);
}

// round 7
// speedup vs baseline: 27.4063x; 1.4832x over previous
#include <cuda_runtime.h>
#include <cuda_fp16.h>
#include <cstdint>

#define BB 8
#define NN 160
#define DD 128
#define HH 8
#define ROWS_TOTAL (BB*NN*NN)   // 204800

// ---------------- scratch ----------------
__device__ float g_s_in [ROWS_TOTAL*HH];     // [b, j, h, i] contiguous in i
__device__ float g_s_out[ROWS_TOTAL*HH];     // [b, i, h, j] contiguous in j
__device__ float g_we_in [BB*NN*1024];       // [bn][h*128+c]
__device__ float g_we_out[BB*NN*1024];
__device__ float g_x1[BB*NN*DD];
__device__ float g_ff[BB*NN*512];
__device__ float g_xi[BB*NN*DD];
__device__ float g_xj[BB*NN*DD];
__device__ float g_cbias[DD];
// pre-converted half weights
__device__ __align__(16) __half g_whqk[4][128*136];   // padded stride 136 (qi,ki,qo,ko)
__device__ __align__(16) __half g_wf1[128*512];
__device__ __align__(16) __half g_wf2[512*128];
__device__ __align__(16) __half g_wei[128*128];
__device__ __align__(16) __half g_wej[128*128];
__device__ __align__(16) __half g_cin [1024*128];     // composite Wv_in@Wp_in per head
__device__ __align__(16) __half g_cout[1024*128];

// ---------------- mma/ldmatrix helpers ----------------
#define MMA_F16(d, a0,a1,a2,a3, b0,b1)                                       \
    asm("mma.sync.aligned.m16n8k16.row.col.f32.f16.f16.f32 "                 \
        "{%0,%1,%2,%3}, {%4,%5,%6,%7}, {%8,%9}, {%0,%1,%2,%3};"              \
        : "+f"(d[0]),"+f"(d[1]),"+f"(d[2]),"+f"(d[3])                        \
        : "r"(a0),"r"(a1),"r"(a2),"r"(a3),"r"(b0),"r"(b1))

__device__ __forceinline__ void ldsm4(uint32_t addr, uint32_t& r0, uint32_t& r1,
                                      uint32_t& r2, uint32_t& r3) {
    asm volatile("ldmatrix.sync.aligned.m8n8.x4.shared.b16 {%0,%1,%2,%3}, [%4];"
                 : "=r"(r0),"=r"(r1),"=r"(r2),"=r"(r3) : "r"(addr));
}
__device__ __forceinline__ void ldsm4t(uint32_t addr, uint32_t& r0, uint32_t& r1,
                                       uint32_t& r2, uint32_t& r3) {
    asm volatile("ldmatrix.sync.aligned.m8n8.x4.trans.shared.b16 {%0,%1,%2,%3}, [%4];"
                 : "=r"(r0),"=r"(r1),"=r"(r2),"=r"(r3) : "r"(addr));
}
__device__ __forceinline__ void cp16(uint32_t dst, const void* src) {
    asm volatile("cp.async.cg.shared.global [%0], [%1], 16;" :: "r"(dst), "l"(src));
}
__device__ __forceinline__ void cp_commit() { asm volatile("cp.async.commit_group;"); }
__device__ __forceinline__ void cp_wait()   { asm volatile("cp.async.wait_group 0;" ::: "memory"); }

// ---------------- precompute kernels ----------------
__global__ void cvtw_kernel(const float* __restrict__ Wqi, const float* __restrict__ Wki,
                            const float* __restrict__ Wqo, const float* __restrict__ Wko,
                            const float* __restrict__ Wf1, const float* __restrict__ Wf2,
                            const float* __restrict__ We) {
    int t = blockIdx.x * 256 + threadIdx.x;
    int reg = blockIdx.y;
    if (reg < 4) {
        if (t < 16384) {
            const float* src = (reg==0)?Wqi:(reg==1)?Wki:(reg==2)?Wqo:Wko;
            int r = t >> 7, c = t & 127;
            g_whqk[reg][r*136 + c] = __float2half_rn(src[t]);
        }
    } else if (reg == 4) { g_wf1[t] = __float2half_rn(Wf1[t]); }
    else if (reg == 5)   { g_wf2[t] = __float2half_rn(Wf2[t]); }
    else if (reg == 6)   { if (t < 16384) g_wei[t] = __float2half_rn(We[t]); }
    else                 { if (t < 16384) g_wej[t] = __float2half_rn(We[16384 + t]); }
}

__global__ void comp_kernel(const float* __restrict__ Wvi, const float* __restrict__ Wpi,
                            const float* __restrict__ Wvo, const float* __restrict__ Wpo) {
    int row = blockIdx.x;          // h*128 + c
    int e = threadIdx.x;
    int h = row >> 7, c = row & 127;
    const float* Wv = blockIdx.y ? Wvo : Wvi;
    const float* Wp = blockIdx.y ? Wpo : Wpi;
    float s = 0.f;
#pragma unroll
    for (int f = 0; f < 16; f++)
        s += Wv[c*128 + 16*h + f] * Wp[(16*h + f)*128 + e];
    (blockIdx.y ? g_cout : g_cin)[row*128 + e] = __float2half_rn(s);
}

__global__ void cbias_kernel(const float* bvi, const float* Wpi, const float* bpi,
                             const float* bvo, const float* Wpo, const float* bpo) {
    int e = threadIdx.x;
    float s = bpi[e] + bpo[e];
    for (int c = 0; c < 128; c++)
        s += bvi[c]*Wpi[c*128+e] + bvo[c]*Wpo[c*128+e];
    g_cbias[e] = s;
}

// =======================================================================
//  FUSED EDGE q/k kernel: 128-row tiles, fp16 mma, scores only
//  smem bytes: W0 [0,34816) W1 [34816,69632) A [69632,104448)
// =======================================================================
__device__ __forceinline__ void prefetch_slab(const __half* src, uint32_t dstb, int tid) {
#pragma unroll
    for (int it = 0; it < 9; it++) {
        int idx = tid + it * 256;                  // 2176 16B chunks
        if (idx < 2176) cp16(dstb + idx*16, src + idx*8);
    }
    cp_commit();
}

__device__ __forceinline__ void qpass(uint32_t Ab, uint32_t Wb, int R0, int C0,
                                      int lm_r, int lm_c, float (&acc)[2][8][4]) {
#pragma unroll
    for (int i = 0; i < 2; i++)
#pragma unroll
        for (int j = 0; j < 8; j++)
#pragma unroll
            for (int t = 0; t < 4; t++) acc[i][j][t] = 0.f;
#pragma unroll 1
    for (int kc = 0; kc < 8; kc++) {
        int k0 = kc * 16;
        uint32_t a[2][4];
#pragma unroll
        for (int i = 0; i < 2; i++)
            ldsm4(Ab + (uint32_t)(((R0 + 16*i + lm_r)*136 + k0 + lm_c)*2),
                  a[i][0], a[i][1], a[i][2], a[i][3]);
        uint32_t b[8][2];
#pragma unroll
        for (int jj = 0; jj < 4; jj++) {
            uint32_t r0,r1,r2,r3;
            ldsm4t(Wb + (uint32_t)(((k0 + lm_r)*136 + C0 + 16*jj + lm_c)*2), r0,r1,r2,r3);
            b[2*jj][0]=r0; b[2*jj][1]=r1; b[2*jj+1][0]=r2; b[2*jj+1][1]=r3;
        }
#pragma unroll
        for (int i = 0; i < 2; i++)
#pragma unroll
            for (int j = 0; j < 8; j++)
                MMA_F16(acc[i][j], a[i][0],a[i][1],a[i][2],a[i][3], b[j][0], b[j][1]);
    }
}

__device__ __forceinline__ void kpass_scores(uint32_t Ab, uint32_t Wb,
        const float (&accQ)[2][8][4],
        const float* __restrict__ bq, const float* __restrict__ bk,
        float* __restrict__ sdst, int swap,
        int rowbase, int R0, int C0, int g, int tg, int lm_r, int lm_c) {
#pragma unroll 1
    for (int jj = 0; jj < 4; jj++) {
        float acck[2][2][4];
#pragma unroll
        for (int i = 0; i < 2; i++)
#pragma unroll
            for (int j2 = 0; j2 < 2; j2++)
#pragma unroll
                for (int t = 0; t < 4; t++) acck[i][j2][t] = 0.f;
#pragma unroll 1
        for (int kc = 0; kc < 8; kc++) {
            int k0 = kc * 16;
            uint32_t a[2][4];
#pragma unroll
            for (int i = 0; i < 2; i++)
                ldsm4(Ab + (uint32_t)(((R0 + 16*i + lm_r)*136 + k0 + lm_c)*2),
                      a[i][0], a[i][1], a[i][2], a[i][3]);
            uint32_t b0,b1,b2,b3;
            ldsm4t(Wb + (uint32_t)(((k0 + lm_r)*136 + C0 + 16*jj + lm_c)*2), b0,b1,b2,b3);
#pragma unroll
            for (int i = 0; i < 2; i++) {
                MMA_F16(acck[i][0], a[i][0],a[i][1],a[i][2],a[i][3], b0, b1);
                MMA_F16(acck[i][1], a[i][0],a[i][1],a[i][2],a[i][3], b2, b3);
            }
        }
        float sc[2][2] = {{0.f,0.f},{0.f,0.f}};
#pragma unroll
        for (int i = 0; i < 2; i++)
#pragma unroll
            for (int j2 = 0; j2 < 2; j2++) {
                int colg = C0 + 16*jj + 8*j2 + 2*tg;
                float bq0 = bq[colg], bq1 = bq[colg+1];
                float bk0 = bk[colg], bk1 = bk[colg+1];
                const float* q = accQ[i][2*jj + j2];
                sc[i][0] += (q[0]+bq0)*(acck[i][j2][0]+bk0) + (q[1]+bq1)*(acck[i][j2][1]+bk1);
                sc[i][1] += (q[2]+bq0)*(acck[i][j2][2]+bk0) + (q[3]+bq1)*(acck[i][j2][3]+bk1);
            }
        int h = (C0 >> 4) + jj;
#pragma unroll
        for (int i = 0; i < 2; i++)
#pragma unroll
            for (int hf = 0; hf < 2; hf++) {
                float v = sc[i][hf];
                v += __shfl_xor_sync(0xffffffffu, v, 1);
                v += __shfl_xor_sync(0xffffffffu, v, 2);
                if (tg == 0) {
                    int grow = rowbase + R0 + 16*i + 8*hf + g;
                    int b = grow / (NN*NN);
                    int rem = grow - b*NN*NN;
                    int ii = rem / NN;
                    int jn = rem - ii*NN;
                    int r1 = swap ? jn : ii;
                    int r2 = swap ? ii : jn;
                    sdst[((b*NN + r1)*HH + h)*NN + r2] = v * 0.25f;
                }
            }
    }
}

__global__ void __launch_bounds__(256, 2) fused_edge_kernel(
    const float* __restrict__ edge,
    const float* __restrict__ bqi, const float* __restrict__ bki,
    const float* __restrict__ bqo, const float* __restrict__ bko)
{
    extern __shared__ __half smh[];
    uint32_t sb = (uint32_t)__cvta_generic_to_shared(smh);
    uint32_t W0b = sb, W1b = sb + 34816, Ab = sb + 69632;
    __half* A_h = smh + 34816;   // halves offset of byte 69632

    int tid = threadIdx.x, lane = tid & 31, wid = tid >> 5;
    int g = lane >> 2, tg = lane & 3;
    int lm_r = ((lane >> 3) & 1) * 8 + (lane & 7);
    int lm_c = (lane >> 4) * 8;
    int R0 = (wid >> 1) * 32, C0 = (wid & 1) * 64;
    int rowbase = blockIdx.x * 128;

    prefetch_slab(g_whqk[0], W0b, tid);      // q_in

    // load + convert E tile (128 x 128 fp32 -> fp16)
    const float4* Eg = (const float4*)(edge + (long)rowbase * DD);
#pragma unroll
    for (int it = 0; it < 16; it++) {
        int idx = tid + it * 256;            // 4096 float4
        int r = idx >> 5, c4 = idx & 31;
        float4 v = Eg[idx];
        __half2 h01 = __floats2half2_rn(v.x, v.y);
        __half2 h23 = __floats2half2_rn(v.z, v.w);
        uint2 u;
        u.x = *reinterpret_cast<uint32_t*>(&h01);
        u.y = *reinterpret_cast<uint32_t*>(&h23);
        *reinterpret_cast<uint2*>(&A_h[r*136 + c4*4]) = u;
    }
    cp_wait(); __syncthreads();
    prefetch_slab(g_whqk[1], W1b, tid);      // k_in

    float accQ[2][8][4];
    qpass(Ab, W0b, R0, C0, lm_r, lm_c, accQ);

    cp_wait(); __syncthreads();
    prefetch_slab(g_whqk[2], W0b, tid);      // q_out
    kpass_scores(Ab, W1b, accQ, bqi, bki, g_s_in, 1, rowbase, R0, C0, g, tg, lm_r, lm_c);

    cp_wait(); __syncthreads();
    prefetch_slab(g_whqk[3], W1b, tid);      // k_out
    qpass(Ab, W0b, R0, C0, lm_r, lm_c, accQ);

    cp_wait(); __syncthreads();
    kpass_scores(Ab, W1b, accQ, bqo, bko, g_s_out, 0, rowbase, R0, C0, g, tg, lm_r, lm_c);
}

// =======================================================================
//  wsum: fused softmax + weighted edge reduction -> we[bn][h*128+e]
// =======================================================================
__global__ void __launch_bounds__(256) wsum_kernel(const float* __restrict__ edge) {
    __shared__ float a_s[HH][NN];
    __shared__ float part[HH][DD];
    int tid = threadIdx.x;
    int bn = blockIdx.x;
    int dir = blockIdx.y;
    int b = bn / NN, n = bn % NN;
    const float* s = dir ? g_s_out : g_s_in;
    long sbase = (long)bn * HH * NN;
    int wid = tid >> 5, lane = tid & 31;
    {   // softmax: warp wid owns head row wid (160 elems)
        float v[5];
#pragma unroll
        for (int t = 0; t < 5; t++) v[t] = s[sbase + wid*NN + lane + 32*t];
        float mx = v[0];
#pragma unroll
        for (int t = 1; t < 5; t++) mx = fmaxf(mx, v[t]);
#pragma unroll
        for (int o = 16; o > 0; o >>= 1) mx = fmaxf(mx, __shfl_xor_sync(0xffffffffu, mx, o));
        float sum = 0.f;
#pragma unroll
        for (int t = 0; t < 5; t++) { v[t] = __expf(v[t] - mx); sum += v[t]; }
#pragma unroll
        for (int o = 16; o > 0; o >>= 1) sum += __shfl_xor_sync(0xffffffffu, sum, o);
        float inv = __frcp_rn(sum);
#pragma unroll
        for (int t = 0; t < 5; t++) a_s[wid][lane + 32*t] = v[t] * inv;
    }
    __syncthreads();
    int e = tid & 127, half_ = tid >> 7;
    float acc[8] = {0.f,0.f,0.f,0.f,0.f,0.f,0.f,0.f};
    long stride = dir ? (long)DD : (long)NN * DD;
    const float* p = dir ? (edge + ((long)(b*NN + n) * NN) * DD + e)
                         : (edge + ((long)b*NN*NN + n) * DD + e);
    int i0 = half_ * 80;
    p += (long)i0 * stride;
#pragma unroll 4
    for (int t = 0; t < 80; t++) {
        float ev = *p; p += stride;
        int i = i0 + t;
#pragma unroll
        for (int h = 0; h < 8; h++) acc[h] += a_s[h][i] * ev;
    }
    if (half_ == 1) {
#pragma unroll
        for (int h = 0; h < 8; h++) part[h][e] = acc[h];
    }
    __syncthreads();
    if (half_ == 0) {
        float* we = dir ? g_we_out : g_we_in;
#pragma unroll
        for (int h = 0; h < 8; h++)
            we[(long)bn * 1024 + h*128 + e] = acc[h] + part[h][e];
    }
}

// =======================================================================
//  generic fp16 GEMM: 64x128 block tile, 8 warps 32x32
//  smem: B [0,34816) A [34816,52224) Cs f32 [52224, +33792)
// =======================================================================
#define GSM_BYTES (34816 + 17408 + 64*132*4)

__device__ __forceinline__ void gmma(uint32_t Ab, uint32_t Bb, int R0, int C0,
                                     int lm_r, int lm_c, float (&acc)[2][4][4]) {
#pragma unroll 1
    for (int kc = 0; kc < 8; kc++) {
        int k0 = kc * 16;
        uint32_t a[2][4];
#pragma unroll
        for (int i = 0; i < 2; i++)
            ldsm4(Ab + (uint32_t)(((R0 + 16*i + lm_r)*136 + k0 + lm_c)*2),
                  a[i][0], a[i][1], a[i][2], a[i][3]);
        uint32_t b[4][2];
#pragma unroll
        for (int jj = 0; jj < 2; jj++) {
            uint32_t r0,r1,r2,r3;
            ldsm4t(Bb + (uint32_t)(((k0 + lm_r)*136 + C0 + 16*jj + lm_c)*2), r0,r1,r2,r3);
            b[2*jj][0]=r0; b[2*jj][1]=r1; b[2*jj+1][0]=r2; b[2*jj+1][1]=r3;
        }
#pragma unroll
        for (int i = 0; i < 2; i++)
#pragma unroll
            for (int j = 0; j < 4; j++)
                MMA_F16(acc[i][j], a[i][0],a[i][1],a[i][2],a[i][3], b[j][0], b[j][1]);
    }
}

__global__ void __launch_bounds__(256) gemm_f16_kernel(
    const float* __restrict__ A,  const __half* __restrict__ Bw,
    const float* __restrict__ A2, const __half* __restrict__ B2w,
    const float* __restrict__ bias, const float* __restrict__ resid,
    float* __restrict__ C, float* __restrict__ C2,
    const float* __restrict__ gam, const float* __restrict__ bet,
    int N, int K1, int K2, int relu, int dualout)
{
    extern __shared__ char smc[];
    uint32_t sb = (uint32_t)__cvta_generic_to_shared(smc);
    uint32_t Bb = sb, Ab = sb + 34816;
    __half* A_h = (__half*)(smc + 34816);
    float* Cs = (float*)(smc + 52224);
    int tid = threadIdx.x, lane = tid & 31, wid = tid >> 5;
    int g = lane >> 2, tg = lane & 3;
    int lm_r = ((lane >> 3) & 1) * 8 + (lane & 7);
    int lm_c = (lane >> 4) * 8;
    int R0 = (wid >> 2) * 32, C0 = (wid & 3) * 32;
    int rowbase = blockIdx.x * 64;
    int colbase = dualout ? 0 : blockIdx.y * 128;
    const __half* Bsel = (dualout && blockIdx.y == 1) ? B2w : Bw;
    float* Csel = (dualout && blockIdx.y == 1) ? C2 : C;

    float acc[2][4][4];
#pragma unroll
    for (int i = 0; i < 2; i++)
#pragma unroll
        for (int j = 0; j < 4; j++)
#pragma unroll
            for (int t = 0; t < 4; t++) acc[i][j][t] = 0.f;

    int nc1 = K1 >> 7;
    int nc2 = (A2 && !dualout) ? (K2 >> 7) : 0;
    for (int c = 0; c < nc1 + nc2; c++) {
        const float* Ap; const __half* Bp; int lda, kb;
        if (c < nc1) { Ap = A;  Bp = Bsel; lda = K1; kb = c << 7; }
        else         { Ap = A2; Bp = B2w;  lda = K2; kb = (c - nc1) << 7; }
        if (c) __syncthreads();
        // B chunk via cp.async: 128 rows x 256B
#pragma unroll
        for (int it = 0; it < 8; it++) {
            int idx = tid + it * 256;      // 2048 chunks
            int r = idx >> 4, c8 = idx & 15;
            cp16(Bb + (uint32_t)((r*136 + c8*8)*2), Bp + (long)(kb + r)*N + colbase + c8*8);
        }
        cp_commit();
        // A chunk fp32 -> fp16  (64 rows x 128 cols = 2048 float4)
#pragma unroll
        for (int it = 0; it < 8; it++) {
            int idx = tid + it * 256;      // 2048 float4
            int r = idx >> 5, c4 = idx & 31;
            float4 v = *(const float4*)&Ap[(long)(rowbase + r)*lda + kb + c4*4];
            __half2 h01 = __floats2half2_rn(v.x, v.y);
            __half2 h23 = __floats2half2_rn(v.z, v.w);
            uint2 u;
            u.x = *reinterpret_cast<uint32_t*>(&h01);
            u.y = *reinterpret_cast<uint32_t*>(&h23);
            *reinterpret_cast<uint2*>(&A_h[r*136 + c4*4]) = u;
        }
        cp_wait();
        __syncthreads();
        gmma(Ab, Bb, R0, C0, lm_r, lm_c, acc);
    }

#pragma unroll
    for (int i = 0; i < 2; i++)
#pragma unroll
        for (int j = 0; j < 4; j++) {
            int cl = C0 + 8*j + 2*tg;
            int cg_ = colbase + cl;
            float b0 = 0.f, b1 = 0.f;
            if (bias) { b0 = bias[cg_]; b1 = bias[cg_ + 1]; }
            long r0 = rowbase + R0 + 16*i + g;
            long r1 = r0 + 8;
            float v00 = acc[i][j][0] + b0, v01 = acc[i][j][1] + b1;
            float v10 = acc[i][j][2] + b0, v11 = acc[i][j][3] + b1;
            if (resid) {
                float2 q0 = *(const float2*)&resid[r0 * N + cg_];
                float2 q1 = *(const float2*)&resid[r1 * N + cg_];
                v00 += q0.x; v01 += q0.y; v10 += q1.x; v11 += q1.y;
            }
            if (relu) {
                v00 = fmaxf(v00, 0.f); v01 = fmaxf(v01, 0.f);
                v10 = fmaxf(v10, 0.f); v11 = fmaxf(v11, 0.f);
            }
            if (gam) {
                int lr0 = R0 + 16*i + g, lr1 = lr0 + 8;
                *(float2*)&Cs[lr0 * 132 + cl] = make_float2(v00, v01);
                *(float2*)&Cs[lr1 * 132 + cl] = make_float2(v10, v11);
            } else {
                *(float2*)&Csel[r0 * N + cg_] = make_float2(v00, v01);
                *(float2*)&Csel[r1 * N + cg_] = make_float2(v10, v11);
            }
        }

    if (gam) {
        __syncthreads();
#pragma unroll
        for (int r = 0; r < 8; r++) {
            int row = wid * 8 + r;
            float4 v = *(const float4*)&Cs[row * 132 + lane * 4];
            float s = v.x + v.y + v.z + v.w;
#pragma unroll
            for (int o = 16; o > 0; o >>= 1) s += __shfl_xor_sync(0xffffffffu, s, o);
            float mean = s * (1.f / 128.f);
            float4 dd = make_float4(v.x - mean, v.y - mean, v.z - mean, v.w - mean);
            float q = dd.x*dd.x + dd.y*dd.y + dd.z*dd.z + dd.w*dd.w;
#pragma unroll
            for (int o = 16; o > 0; o >>= 1) q += __shfl_xor_sync(0xffffffffu, q, o);
            float rs = rsqrtf(q * (1.f / 128.f) + 1e-5f);
            float4 gg = ((const float4*)gam)[lane];
            float4 bb = ((const float4*)bet)[lane];
            float4 o4;
            o4.x = dd.x*rs*gg.x + bb.x;
            o4.y = dd.y*rs*gg.y + bb.y;
            o4.z = dd.z*rs*gg.z + bb.z;
            o4.w = dd.w*rs*gg.w + bb.w;
            *(float4*)&C[((long)rowbase + row) * 128 + lane * 4] = o4;
        }
    }
}

// ---------------- edge_out broadcast ----------------
__global__ void edge_out_kernel(const float* __restrict__ b_edge, float* __restrict__ dst) {
    long gid = (long)blockIdx.x * blockDim.x + threadIdx.x;
    int e4 = (int)(gid & 31);
    long rem = gid >> 5;
    int j = (int)(rem % NN);
    long rem2 = rem / NN;
    int i = (int)(rem2 % NN);
    int b = (int)(rem2 / NN);
    float4 xi = ((const float4*)g_xi)[(b * NN + i) * 32 + e4];
    float4 xj = ((const float4*)g_xj)[(b * NN + j) * 32 + e4];
    float4 be = ((const float4*)b_edge)[e4];
    float4 o;
    o.x = xi.x + xj.x + be.x;
    o.y = xi.y + xj.y + be.y;
    o.z = xi.z + xj.z + be.z;
    o.w = xi.w + xj.w + be.w;
    ((float4*)dst)[gid] = o;
}

// ---------------- launch ----------------
extern "C" void kernel_launch(void* const* d_in, const int* in_sizes, int n_in,
                              void* d_out, int out_size) {
    const float* node   = (const float*)d_in[0];
    const float* edge   = (const float*)d_in[1];
    const float* Wqi = (const float*)d_in[2];  const float* bqi = (const float*)d_in[3];
    const float* Wki = (const float*)d_in[4];  const float* bki = (const float*)d_in[5];
    const float* Wvi = (const float*)d_in[6];  const float* bvi = (const float*)d_in[7];
    const float* Wqo = (const float*)d_in[8];  const float* bqo = (const float*)d_in[9];
    const float* Wko = (const float*)d_in[10]; const float* bko = (const float*)d_in[11];
    const float* Wvo = (const float*)d_in[12]; const float* bvo = (const float*)d_in[13];
    const float* Wpi = (const float*)d_in[14]; const float* bpi = (const float*)d_in[15];
    const float* Wpo = (const float*)d_in[16]; const float* bpo = (const float*)d_in[17];
    const float* Wf1 = (const float*)d_in[18]; const float* bf1 = (const float*)d_in[19];
    const float* Wf2 = (const float*)d_in[20]; const float* bf2 = (const float*)d_in[21];
    const float* g1  = (const float*)d_in[22]; const float* be1 = (const float*)d_in[23];
    const float* g2  = (const float*)d_in[24]; const float* be2 = (const float*)d_in[25];
    const float* Wedge = (const float*)d_in[26];
    const float* bedge = (const float*)d_in[27];
    float* out = (float*)d_out;

    float* p_wein; cudaGetSymbolAddress((void**)&p_wein, g_we_in);
    float* p_weout; cudaGetSymbolAddress((void**)&p_weout, g_we_out);
    float* p_x1;   cudaGetSymbolAddress((void**)&p_x1, g_x1);
    float* p_ff;   cudaGetSymbolAddress((void**)&p_ff, g_ff);
    float* p_xi;   cudaGetSymbolAddress((void**)&p_xi, g_xi);
    float* p_xj;   cudaGetSymbolAddress((void**)&p_xj, g_xj);
    float* p_cb;   cudaGetSymbolAddress((void**)&p_cb, g_cbias);
    __half* p_cin;  cudaGetSymbolAddress((void**)&p_cin, g_cin);
    __half* p_cout; cudaGetSymbolAddress((void**)&p_cout, g_cout);
    __half* p_f1;   cudaGetSymbolAddress((void**)&p_f1, g_wf1);
    __half* p_f2;   cudaGetSymbolAddress((void**)&p_f2, g_wf2);
    __half* p_ei;   cudaGetSymbolAddress((void**)&p_ei, g_wei);
    __half* p_ej;   cudaGetSymbolAddress((void**)&p_ej, g_wej);

    cudaFuncSetAttribute(fused_edge_kernel,
                         cudaFuncAttributeMaxDynamicSharedMemorySize, 104448);
    cudaFuncSetAttribute(gemm_f16_kernel,
                         cudaFuncAttributeMaxDynamicSharedMemorySize, GSM_BYTES);

    // precompute: weight conversion + composites + combined bias
    cvtw_kernel<<<dim3(256, 8), 256>>>(Wqi, Wki, Wqo, Wko, Wf1, Wf2, Wedge);
    comp_kernel<<<dim3(1024, 2), 128>>>(Wvi, Wpi, Wvo, Wpo);
    cbias_kernel<<<1, 128>>>(bvi, Wpi, bpi, bvo, Wpo, bpo);

    // 1) q/k projections + scores
    fused_edge_kernel<<<ROWS_TOTAL / 128, 256, 104448>>>(edge, bqi, bki, bqo, bko);

    // 2) fused softmax + weighted edge sums
    wsum_kernel<<<dim3(BB * NN, 2), 256>>>(edge);

    // 3) x1 = LN(we_in@Cin + we_out@Cout + cbias + node)
    gemm_f16_kernel<<<dim3(BB * NN / 64, 1), 256, GSM_BYTES>>>(
        p_wein, p_cin, p_weout, p_cout, p_cb, node, p_x1, nullptr,
        g1, be1, 128, 1024, 1024, 0, 0);

    // 4) ff = relu(x1@Wf1 + bf1)
    gemm_f16_kernel<<<dim3(BB * NN / 64, 4), 256, GSM_BYTES>>>(
        p_x1, p_f1, nullptr, nullptr, bf1, nullptr, p_ff, nullptr,
        nullptr, nullptr, 512, 128, 0, 1, 0);

    // 5) x2 = LN(ff@Wf2 + bf2 + x1) -> out
    gemm_f16_kernel<<<dim3(BB * NN / 64, 1), 256, GSM_BYTES>>>(
        p_ff, p_f2, nullptr, nullptr, bf2, p_x1, out, nullptr,
        g2, be2, 128, 512, 0, 0, 0);

    // 6) xi = x2@Wi ; xj = x2@Wj
    gemm_f16_kernel<<<dim3(BB * NN / 64, 2), 256, GSM_BYTES>>>(
        out, p_ei, nullptr, p_ej, nullptr, nullptr, p_xi, p_xj,
        nullptr, nullptr, 128, 128, 0, 0, 1);

    // 7) edge_out broadcast
    edge_out_kernel<<<(BB * NN * NN * DD / 4) / 256, 256>>>(bedge, out + BB * NN * DD);
}

// round 8
// speedup vs baseline: 33.4933x; 1.2221x over previous
#include <cuda_runtime.h>
#include <cuda_fp16.h>
#include <cstdint>

#define BB 8
#define NN 160
#define DD 128
#define HH 8
#define ROWS_TOTAL (BB*NN*NN)   // 204800

// ---------------- scratch ----------------
__device__ float g_s_in [ROWS_TOTAL*HH];     // [b, j, h, i] contiguous in i
__device__ float g_s_out[ROWS_TOTAL*HH];     // [b, i, h, j] contiguous in j
__device__ float g_we_in [BB*NN*1024];       // [bn][h*128+c]
__device__ float g_we_out[BB*NN*1024];
__device__ float g_xi[BB*NN*DD];
__device__ float g_xj[BB*NN*DD];
__device__ float g_cbias[DD];
// pre-converted half weights
__device__ __align__(16) __half g_whqk[4][128*136];   // (qi,ki,qo,ko), stride 136
__device__ __align__(16) __half g_wf1[128*512];
__device__ __align__(16) __half g_wf2[512*128];
__device__ __align__(16) __half g_wei[128*128];
__device__ __align__(16) __half g_wej[128*128];
__device__ __align__(16) __half g_cin [1024*128];     // composite Wv_in@Wp_in per head
__device__ __align__(16) __half g_cout[1024*128];

// ---------------- mma/ldmatrix helpers ----------------
#define MMA_F16(d, a0,a1,a2,a3, b0,b1)                                       \
    asm("mma.sync.aligned.m16n8k16.row.col.f32.f16.f16.f32 "                 \
        "{%0,%1,%2,%3}, {%4,%5,%6,%7}, {%8,%9}, {%0,%1,%2,%3};"              \
        : "+f"(d[0]),"+f"(d[1]),"+f"(d[2]),"+f"(d[3])                        \
        : "r"(a0),"r"(a1),"r"(a2),"r"(a3),"r"(b0),"r"(b1))

__device__ __forceinline__ void ldsm4(uint32_t addr, uint32_t& r0, uint32_t& r1,
                                      uint32_t& r2, uint32_t& r3) {
    asm volatile("ldmatrix.sync.aligned.m8n8.x4.shared.b16 {%0,%1,%2,%3}, [%4];"
                 : "=r"(r0),"=r"(r1),"=r"(r2),"=r"(r3) : "r"(addr));
}
__device__ __forceinline__ void ldsm4t(uint32_t addr, uint32_t& r0, uint32_t& r1,
                                       uint32_t& r2, uint32_t& r3) {
    asm volatile("ldmatrix.sync.aligned.m8n8.x4.trans.shared.b16 {%0,%1,%2,%3}, [%4];"
                 : "=r"(r0),"=r"(r1),"=r"(r2),"=r"(r3) : "r"(addr));
}
__device__ __forceinline__ void cp16(uint32_t dst, const void* src) {
    asm volatile("cp.async.cg.shared.global [%0], [%1], 16;" :: "r"(dst), "l"(src));
}
__device__ __forceinline__ void cp_commit() { asm volatile("cp.async.commit_group;"); }
__device__ __forceinline__ void cp_wait()   { asm volatile("cp.async.wait_group 0;" ::: "memory"); }

// ---------------- precompute kernels ----------------
__global__ void cvtw_kernel(const float* __restrict__ Wqi, const float* __restrict__ Wki,
                            const float* __restrict__ Wqo, const float* __restrict__ Wko,
                            const float* __restrict__ Wf1, const float* __restrict__ Wf2,
                            const float* __restrict__ We) {
    int t = blockIdx.x * 256 + threadIdx.x;
    int reg = blockIdx.y;
    if (reg < 4) {
        if (t < 16384) {
            const float* src = (reg==0)?Wqi:(reg==1)?Wki:(reg==2)?Wqo:Wko;
            int r = t >> 7, c = t & 127;
            g_whqk[reg][r*136 + c] = __float2half_rn(src[t]);
        }
    } else if (reg == 4) { g_wf1[t] = __float2half_rn(Wf1[t]); }
    else if (reg == 5)   { g_wf2[t] = __float2half_rn(Wf2[t]); }
    else if (reg == 6)   { if (t < 16384) g_wei[t] = __float2half_rn(We[t]); }
    else                 { if (t < 16384) g_wej[t] = __float2half_rn(We[16384 + t]); }
}

__global__ void comp_kernel(const float* __restrict__ Wvi, const float* __restrict__ Wpi,
                            const float* __restrict__ Wvo, const float* __restrict__ Wpo) {
    int row = blockIdx.x;          // h*128 + c
    int e = threadIdx.x;
    int h = row >> 7, c = row & 127;
    const float* Wv = blockIdx.y ? Wvo : Wvi;
    const float* Wp = blockIdx.y ? Wpo : Wpi;
    float s = 0.f;
#pragma unroll
    for (int f = 0; f < 16; f++)
        s += Wv[c*128 + 16*h + f] * Wp[(16*h + f)*128 + e];
    (blockIdx.y ? g_cout : g_cin)[row*128 + e] = __float2half_rn(s);
}

__global__ void cbias_kernel(const float* bvi, const float* Wpi, const float* bpi,
                             const float* bvo, const float* Wpo, const float* bpo) {
    int e = threadIdx.x;
    float s = bpi[e] + bpo[e];
    for (int c = 0; c < 128; c++)
        s += bvi[c]*Wpi[c*128+e] + bvo[c]*Wpo[c*128+e];
    g_cbias[e] = s;
}

// =======================================================================
//  FUSED EDGE q/k kernel
//  smem bytes: W0 [0,34816) W1 [34816,69632) A [69632,104448)
// =======================================================================
__device__ __forceinline__ void prefetch_slab(const __half* src, uint32_t dstb, int tid) {
#pragma unroll
    for (int it = 0; it < 9; it++) {
        int idx = tid + it * 256;                  // 2176 16B chunks
        if (idx < 2176) cp16(dstb + idx*16, src + idx*8);
    }
    cp_commit();
}

__device__ __forceinline__ void qpass(uint32_t Ab, uint32_t Wb, int R0, int C0,
                                      int lm_r, int lm_c, float (&acc)[2][8][4]) {
#pragma unroll
    for (int i = 0; i < 2; i++)
#pragma unroll
        for (int j = 0; j < 8; j++)
#pragma unroll
            for (int t = 0; t < 4; t++) acc[i][j][t] = 0.f;
#pragma unroll 1
    for (int kc = 0; kc < 8; kc++) {
        int k0 = kc * 16;
        uint32_t a[2][4];
#pragma unroll
        for (int i = 0; i < 2; i++)
            ldsm4(Ab + (uint32_t)(((R0 + 16*i + lm_r)*136 + k0 + lm_c)*2),
                  a[i][0], a[i][1], a[i][2], a[i][3]);
        uint32_t b[8][2];
#pragma unroll
        for (int jj = 0; jj < 4; jj++) {
            uint32_t r0,r1,r2,r3;
            ldsm4t(Wb + (uint32_t)(((k0 + lm_r)*136 + C0 + 16*jj + lm_c)*2), r0,r1,r2,r3);
            b[2*jj][0]=r0; b[2*jj][1]=r1; b[2*jj+1][0]=r2; b[2*jj+1][1]=r3;
        }
#pragma unroll
        for (int i = 0; i < 2; i++)
#pragma unroll
            for (int j = 0; j < 8; j++)
                MMA_F16(acc[i][j], a[i][0],a[i][1],a[i][2],a[i][3], b[j][0], b[j][1]);
    }
}

// pack (q + bias) into half2: qh[i][j][0] = rows g cols(2tg,2tg+1), [1] = row g+8
__device__ __forceinline__ void pack_q(const float (&acc)[2][8][4],
                                       const float* __restrict__ bq,
                                       int C0, int tg, uint32_t (&qh)[2][8][2]) {
#pragma unroll
    for (int i = 0; i < 2; i++)
#pragma unroll
        for (int j = 0; j < 8; j++) {
            int colg = C0 + 8*j + 2*tg;
            float bq0 = bq[colg], bq1 = bq[colg+1];
            __half2 lo = __floats2half2_rn(acc[i][j][0]+bq0, acc[i][j][1]+bq1);
            __half2 hi = __floats2half2_rn(acc[i][j][2]+bq0, acc[i][j][3]+bq1);
            qh[i][j][0] = *reinterpret_cast<uint32_t*>(&lo);
            qh[i][j][1] = *reinterpret_cast<uint32_t*>(&hi);
        }
}

// k pass in head-group pairs: A loaded once per kc (not per group)
__device__ __forceinline__ void kpass_pair(uint32_t Ab, uint32_t Wb,
        const uint32_t (&qh)[2][8][2],
        const float* __restrict__ bk,
        float* __restrict__ sdst, int swap,
        int rowbase, int R0, int C0, int g, int tg, int lm_r, int lm_c) {
#pragma unroll 1
    for (int op = 0; op < 2; op++) {
        float acck[2][4][4];      // [i][2*p + j2][4]
#pragma unroll
        for (int i = 0; i < 2; i++)
#pragma unroll
            for (int j = 0; j < 4; j++)
#pragma unroll
                for (int t = 0; t < 4; t++) acck[i][j][t] = 0.f;
#pragma unroll 1
        for (int kc = 0; kc < 8; kc++) {
            int k0 = kc * 16;
            uint32_t a[2][4];
#pragma unroll
            for (int i = 0; i < 2; i++)
                ldsm4(Ab + (uint32_t)(((R0 + 16*i + lm_r)*136 + k0 + lm_c)*2),
                      a[i][0], a[i][1], a[i][2], a[i][3]);
#pragma unroll
            for (int p = 0; p < 2; p++) {
                int jj = 2*op + p;
                uint32_t b0,b1,b2,b3;
                ldsm4t(Wb + (uint32_t)(((k0 + lm_r)*136 + C0 + 16*jj + lm_c)*2), b0,b1,b2,b3);
#pragma unroll
                for (int i = 0; i < 2; i++) {
                    MMA_F16(acck[i][2*p],   a[i][0],a[i][1],a[i][2],a[i][3], b0, b1);
                    MMA_F16(acck[i][2*p+1], a[i][0],a[i][1],a[i][2],a[i][3], b2, b3);
                }
            }
        }
        // score epilogue for heads jj = 2*op + p
#pragma unroll
        for (int i = 0; i < 2; i++)
#pragma unroll
            for (int p = 0; p < 2; p++) {
                float sc0 = 0.f, sc1 = 0.f;
#pragma unroll
                for (int j2 = 0; j2 < 2; j2++) {
                    int colg = C0 + 16*(2*op+p) + 8*j2 + 2*tg;
                    float bk0 = bk[colg], bk1 = bk[colg+1];
                    const uint32_t* q = qh[i][4*op + 2*p + j2];
                    float2 qlo = __half22float2(*reinterpret_cast<const __half2*>(&q[0]));
                    float2 qhi = __half22float2(*reinterpret_cast<const __half2*>(&q[1]));
                    const float* k = acck[i][2*p + j2];
                    sc0 += qlo.x*(k[0]+bk0) + qlo.y*(k[1]+bk1);
                    sc1 += qhi.x*(k[2]+bk0) + qhi.y*(k[3]+bk1);
                }
                sc0 += __shfl_xor_sync(0xffffffffu, sc0, 1);
                sc0 += __shfl_xor_sync(0xffffffffu, sc0, 2);
                sc1 += __shfl_xor_sync(0xffffffffu, sc1, 1);
                sc1 += __shfl_xor_sync(0xffffffffu, sc1, 2);
                if (tg == 0) {
                    int h = (C0 >> 4) + 2*op + p;
#pragma unroll
                    for (int hf = 0; hf < 2; hf++) {
                        float v = hf ? sc1 : sc0;
                        int grow = rowbase + R0 + 16*i + 8*hf + g;
                        int b = grow / (NN*NN);
                        int rem = grow - b*NN*NN;
                        int ii = rem / NN;
                        int jn = rem - ii*NN;
                        int r1 = swap ? jn : ii;
                        int r2 = swap ? ii : jn;
                        sdst[((b*NN + r1)*HH + h)*NN + r2] = v * 0.25f;
                    }
                }
            }
    }
}

__global__ void __launch_bounds__(256, 2) fused_edge_kernel(
    const float* __restrict__ edge,
    const float* __restrict__ bqi, const float* __restrict__ bki,
    const float* __restrict__ bqo, const float* __restrict__ bko)
{
    extern __shared__ __half smh[];
    uint32_t sb = (uint32_t)__cvta_generic_to_shared(smh);
    uint32_t W0b = sb, W1b = sb + 34816, Ab = sb + 69632;
    __half* A_h = smh + 34816;   // halves offset of byte 69632

    int tid = threadIdx.x, lane = tid & 31, wid = tid >> 5;
    int g = lane >> 2, tg = lane & 3;
    int lm_r = ((lane >> 3) & 1) * 8 + (lane & 7);
    int lm_c = (lane >> 4) * 8;
    int R0 = (wid >> 1) * 32, C0 = (wid & 1) * 64;
    int rowbase = blockIdx.x * 128;

    prefetch_slab(g_whqk[0], W0b, tid);      // q_in

    const float4* Eg = (const float4*)(edge + (long)rowbase * DD);
#pragma unroll
    for (int it = 0; it < 16; it++) {
        int idx = tid + it * 256;
        int r = idx >> 5, c4 = idx & 31;
        float4 v = Eg[idx];
        __half2 h01 = __floats2half2_rn(v.x, v.y);
        __half2 h23 = __floats2half2_rn(v.z, v.w);
        uint2 u;
        u.x = *reinterpret_cast<uint32_t*>(&h01);
        u.y = *reinterpret_cast<uint32_t*>(&h23);
        *reinterpret_cast<uint2*>(&A_h[r*136 + c4*4]) = u;
    }
    cp_wait(); __syncthreads();
    prefetch_slab(g_whqk[1], W1b, tid);      // k_in

    uint32_t qh[2][8][2];
    {
        float accQ[2][8][4];
        qpass(Ab, W0b, R0, C0, lm_r, lm_c, accQ);
        pack_q(accQ, bqi, C0, tg, qh);
    }
    cp_wait(); __syncthreads();
    prefetch_slab(g_whqk[2], W0b, tid);      // q_out
    kpass_pair(Ab, W1b, qh, bki, g_s_in, 1, rowbase, R0, C0, g, tg, lm_r, lm_c);

    cp_wait(); __syncthreads();
    prefetch_slab(g_whqk[3], W1b, tid);      // k_out
    {
        float accQ[2][8][4];
        qpass(Ab, W0b, R0, C0, lm_r, lm_c, accQ);
        pack_q(accQ, bqo, C0, tg, qh);
    }
    cp_wait(); __syncthreads();
    kpass_pair(Ab, W1b, qh, bko, g_s_out, 0, rowbase, R0, C0, g, tg, lm_r, lm_c);
}

// =======================================================================
//  wsum: fused softmax + weighted edge reduction -> we[bn][h*128+e]
// =======================================================================
__global__ void __launch_bounds__(256) wsum_kernel(const float* __restrict__ edge) {
    __shared__ float a_s[HH][NN];
    __shared__ float part[HH][DD];
    int tid = threadIdx.x;
    int bn = blockIdx.x;
    int dir = blockIdx.y;
    int b = bn / NN, n = bn % NN;
    const float* s = dir ? g_s_out : g_s_in;
    long sbase = (long)bn * HH * NN;
    int wid = tid >> 5, lane = tid & 31;
    {
        float v[5];
#pragma unroll
        for (int t = 0; t < 5; t++) v[t] = s[sbase + wid*NN + lane + 32*t];
        float mx = v[0];
#pragma unroll
        for (int t = 1; t < 5; t++) mx = fmaxf(mx, v[t]);
#pragma unroll
        for (int o = 16; o > 0; o >>= 1) mx = fmaxf(mx, __shfl_xor_sync(0xffffffffu, mx, o));
        float sum = 0.f;
#pragma unroll
        for (int t = 0; t < 5; t++) { v[t] = __expf(v[t] - mx); sum += v[t]; }
#pragma unroll
        for (int o = 16; o > 0; o >>= 1) sum += __shfl_xor_sync(0xffffffffu, sum, o);
        float inv = __frcp_rn(sum);
#pragma unroll
        for (int t = 0; t < 5; t++) a_s[wid][lane + 32*t] = v[t] * inv;
    }
    __syncthreads();
    int e = tid & 127, half_ = tid >> 7;
    float acc[8] = {0.f,0.f,0.f,0.f,0.f,0.f,0.f,0.f};
    long stride = dir ? (long)DD : (long)NN * DD;
    const float* p = dir ? (edge + ((long)(b*NN + n) * NN) * DD + e)
                         : (edge + ((long)b*NN*NN + n) * DD + e);
    int i0 = half_ * 80;
    p += (long)i0 * stride;
#pragma unroll 4
    for (int t = 0; t < 80; t++) {
        float ev = __ldcs(p); p += stride;
        int i = i0 + t;
#pragma unroll
        for (int h = 0; h < 8; h++) acc[h] += a_s[h][i] * ev;
    }
    if (half_ == 1) {
#pragma unroll
        for (int h = 0; h < 8; h++) part[h][e] = acc[h];
    }
    __syncthreads();
    if (half_ == 0) {
        float* we = dir ? g_we_out : g_we_in;
#pragma unroll
        for (int h = 0; h < 8; h++)
            we[(long)bn * 1024 + h*128 + e] = acc[h] + part[h][e];
    }
}

// =======================================================================
//  node_chain: ONE kernel for x1 = LN(we@C + node) -> ff -> x2 -> xi/xj
//  smem: B[0,34816) Ah[34816,52224) Cs[52224,86016) x1h[86016,103424)
//        x1f[103424,136192) ffh[136192,202752)  (ffh stride 520 halves)
// =======================================================================
#define NSM_B    0
#define NSM_A    34816
#define NSM_CS   52224
#define NSM_X1H  86016
#define NSM_X1F  103424
#define NSM_FFH  136192
#define NSM_TOTAL 202752

__device__ __forceinline__ void gmma_g(uint32_t Ab, int astride, uint32_t Bb,
                                       int R0, int C0, int lm_r, int lm_c,
                                       float (&acc)[2][4][4]) {
#pragma unroll 1
    for (int kc = 0; kc < 8; kc++) {
        int k0 = kc * 16;
        uint32_t a[2][4];
#pragma unroll
        for (int i = 0; i < 2; i++)
            ldsm4(Ab + (uint32_t)(((R0 + 16*i + lm_r)*astride + k0 + lm_c)*2),
                  a[i][0], a[i][1], a[i][2], a[i][3]);
        uint32_t b[4][2];
#pragma unroll
        for (int jj = 0; jj < 2; jj++) {
            uint32_t r0,r1,r2,r3;
            ldsm4t(Bb + (uint32_t)(((k0 + lm_r)*136 + C0 + 16*jj + lm_c)*2), r0,r1,r2,r3);
            b[2*jj][0]=r0; b[2*jj][1]=r1; b[2*jj+1][0]=r2; b[2*jj+1][1]=r3;
        }
#pragma unroll
        for (int i = 0; i < 2; i++)
#pragma unroll
            for (int j = 0; j < 4; j++)
                MMA_F16(acc[i][j], a[i][0],a[i][1],a[i][2],a[i][3], b[j][0], b[j][1]);
    }
}

__device__ __forceinline__ void zacc(float (&acc)[2][4][4]) {
#pragma unroll
    for (int i = 0; i < 2; i++)
#pragma unroll
        for (int j = 0; j < 4; j++)
#pragma unroll
            for (int t = 0; t < 4; t++) acc[i][j][t] = 0.f;
}

__global__ void __launch_bounds__(256) node_chain_kernel(
    const float* __restrict__ node,
    const float* __restrict__ bf1, const float* __restrict__ bf2,
    const float* __restrict__ g1,  const float* __restrict__ be1,
    const float* __restrict__ g2,  const float* __restrict__ be2,
    float* __restrict__ out_x)
{
    extern __shared__ char smc[];
    uint32_t sb = (uint32_t)__cvta_generic_to_shared(smc);
    uint32_t Bb = sb + NSM_B, Ab = sb + NSM_A, X1Hb = sb + NSM_X1H, FFHb = sb + NSM_FFH;
    __half* A_h  = (__half*)(smc + NSM_A);
    float*  Cs   = (float*)(smc + NSM_CS);
    __half* x1h  = (__half*)(smc + NSM_X1H);
    float*  x1f  = (float*)(smc + NSM_X1F);
    __half* ffh  = (__half*)(smc + NSM_FFH);
    int tid = threadIdx.x, lane = tid & 31, wid = tid >> 5;
    int g = lane >> 2, tg = lane & 3;
    int lm_r = ((lane >> 3) & 1) * 8 + (lane & 7);
    int lm_c = (lane >> 4) * 8;
    int R0 = (wid >> 2) * 32, C0 = (wid & 3) * 32;
    int rowbase = blockIdx.x * 64;

    float acc[2][4][4];

    // ---- stage A: t = we_in@cin + we_out@cout + cbias + node ; x1 = LN(t)
    zacc(acc);
    for (int c = 0; c < 16; c++) {
        const float* Ap = (c < 8) ? g_we_in : g_we_out;
        const __half* Bp = (c < 8) ? g_cin : g_cout;
        int kb = (c & 7) << 7;
        if (c) __syncthreads();
#pragma unroll
        for (int it = 0; it < 8; it++) {
            int idx = tid + it * 256;
            int r = idx >> 4, c8 = idx & 15;
            cp16(Bb + (uint32_t)((r*136 + c8*8)*2), Bp + (long)(kb + r)*128 + c8*8);
        }
        cp_commit();
#pragma unroll
        for (int it = 0; it < 8; it++) {
            int idx = tid + it * 256;
            int r = idx >> 5, c4 = idx & 31;
            float4 v = *(const float4*)&Ap[(long)(rowbase + r)*1024 + kb + c4*4];
            __half2 h01 = __floats2half2_rn(v.x, v.y);
            __half2 h23 = __floats2half2_rn(v.z, v.w);
            uint2 u;
            u.x = *reinterpret_cast<uint32_t*>(&h01);
            u.y = *reinterpret_cast<uint32_t*>(&h23);
            *reinterpret_cast<uint2*>(&A_h[r*136 + c4*4]) = u;
        }
        cp_wait();
        __syncthreads();
        gmma_g(Ab, 136, Bb, R0, C0, lm_r, lm_c, acc);
    }
#pragma unroll
    for (int i = 0; i < 2; i++)
#pragma unroll
        for (int j = 0; j < 4; j++) {
            int cl = C0 + 8*j + 2*tg;
            int lr0 = R0 + 16*i + g, lr1 = lr0 + 8;
            float2 n0 = *(const float2*)&node[((long)rowbase + lr0)*128 + cl];
            float2 n1 = *(const float2*)&node[((long)rowbase + lr1)*128 + cl];
            float b0 = g_cbias[cl], b1 = g_cbias[cl+1];
            *(float2*)&Cs[lr0*132 + cl] = make_float2(acc[i][j][0]+b0+n0.x, acc[i][j][1]+b1+n0.y);
            *(float2*)&Cs[lr1*132 + cl] = make_float2(acc[i][j][2]+b0+n1.x, acc[i][j][3]+b1+n1.y);
        }
    __syncthreads();
    // LN -> x1f (f32) + x1h (fp16)
#pragma unroll
    for (int r = 0; r < 8; r++) {
        int row = wid * 8 + r;
        float4 v = *(const float4*)&Cs[row*132 + lane*4];
        float s = v.x + v.y + v.z + v.w;
#pragma unroll
        for (int o = 16; o > 0; o >>= 1) s += __shfl_xor_sync(0xffffffffu, s, o);
        float mean = s * (1.f/128.f);
        float4 dd = make_float4(v.x-mean, v.y-mean, v.z-mean, v.w-mean);
        float q = dd.x*dd.x + dd.y*dd.y + dd.z*dd.z + dd.w*dd.w;
#pragma unroll
        for (int o = 16; o > 0; o >>= 1) q += __shfl_xor_sync(0xffffffffu, q, o);
        float rs = rsqrtf(q * (1.f/128.f) + 1e-5f);
        float4 gg = ((const float4*)g1)[lane];
        float4 bb = ((const float4*)be1)[lane];
        float4 o4 = make_float4(dd.x*rs*gg.x+bb.x, dd.y*rs*gg.y+bb.y,
                                dd.z*rs*gg.z+bb.z, dd.w*rs*gg.w+bb.w);
        *(float4*)&x1f[row*128 + lane*4] = o4;
        __half2 ha = __floats2half2_rn(o4.x, o4.y);
        __half2 hb = __floats2half2_rn(o4.z, o4.w);
        uint2 u;
        u.x = *reinterpret_cast<uint32_t*>(&ha);
        u.y = *reinterpret_cast<uint32_t*>(&hb);
        *reinterpret_cast<uint2*>(&x1h[row*136 + lane*4]) = u;
    }
    __syncthreads();

    // ---- stage B: ff = relu(x1@Wf1 + bf1) -> ffh (fp16, stride 520)
    for (int nc = 0; nc < 4; nc++) {
        if (nc) __syncthreads();
#pragma unroll
        for (int it = 0; it < 8; it++) {
            int idx = tid + it * 256;
            int r = idx >> 4, c8 = idx & 15;
            cp16(Bb + (uint32_t)((r*136 + c8*8)*2), g_wf1 + r*512 + nc*128 + c8*8);
        }
        cp_commit(); cp_wait();
        __syncthreads();
        zacc(acc);
        gmma_g(X1Hb, 136, Bb, R0, C0, lm_r, lm_c, acc);
#pragma unroll
        for (int i = 0; i < 2; i++)
#pragma unroll
            for (int j = 0; j < 4; j++) {
                int cl = C0 + 8*j + 2*tg;
                int cg_ = nc*128 + cl;
                float b0 = bf1[cg_], b1 = bf1[cg_+1];
                int lr0 = R0 + 16*i + g, lr1 = lr0 + 8;
                __half2 v0 = __floats2half2_rn(fmaxf(acc[i][j][0]+b0, 0.f), fmaxf(acc[i][j][1]+b1, 0.f));
                __half2 v1 = __floats2half2_rn(fmaxf(acc[i][j][2]+b0, 0.f), fmaxf(acc[i][j][3]+b1, 0.f));
                *reinterpret_cast<uint32_t*>(&ffh[lr0*520 + cg_]) = *reinterpret_cast<uint32_t*>(&v0);
                *reinterpret_cast<uint32_t*>(&ffh[lr1*520 + cg_]) = *reinterpret_cast<uint32_t*>(&v1);
            }
    }
    __syncthreads();

    // ---- stage C: t2 = ff@Wf2 + bf2 + x1 ; x2 = LN(t2) -> out_x + x1h(reuse)
    zacc(acc);
    for (int c = 0; c < 4; c++) {
        int kb = c << 7;
        __syncthreads();
#pragma unroll
        for (int it = 0; it < 8; it++) {
            int idx = tid + it * 256;
            int r = idx >> 4, c8 = idx & 15;
            cp16(Bb + (uint32_t)((r*136 + c8*8)*2), g_wf2 + (long)(kb + r)*128 + c8*8);
        }
        cp_commit(); cp_wait();
        __syncthreads();
        gmma_g(FFHb + (uint32_t)(kb*2), 520, Bb, R0, C0, lm_r, lm_c, acc);
    }
#pragma unroll
    for (int i = 0; i < 2; i++)
#pragma unroll
        for (int j = 0; j < 4; j++) {
            int cl = C0 + 8*j + 2*tg;
            float b0 = bf2[cl], b1 = bf2[cl+1];
            int lr0 = R0 + 16*i + g, lr1 = lr0 + 8;
            float2 r0v = *(const float2*)&x1f[lr0*128 + cl];
            float2 r1v = *(const float2*)&x1f[lr1*128 + cl];
            *(float2*)&Cs[lr0*132 + cl] = make_float2(acc[i][j][0]+b0+r0v.x, acc[i][j][1]+b1+r0v.y);
            *(float2*)&Cs[lr1*132 + cl] = make_float2(acc[i][j][2]+b0+r1v.x, acc[i][j][3]+b1+r1v.y);
        }
    __syncthreads();
#pragma unroll
    for (int r = 0; r < 8; r++) {
        int row = wid * 8 + r;
        float4 v = *(const float4*)&Cs[row*132 + lane*4];
        float s = v.x + v.y + v.z + v.w;
#pragma unroll
        for (int o = 16; o > 0; o >>= 1) s += __shfl_xor_sync(0xffffffffu, s, o);
        float mean = s * (1.f/128.f);
        float4 dd = make_float4(v.x-mean, v.y-mean, v.z-mean, v.w-mean);
        float q = dd.x*dd.x + dd.y*dd.y + dd.z*dd.z + dd.w*dd.w;
#pragma unroll
        for (int o = 16; o > 0; o >>= 1) q += __shfl_xor_sync(0xffffffffu, q, o);
        float rs = rsqrtf(q * (1.f/128.f) + 1e-5f);
        float4 gg = ((const float4*)g2)[lane];
        float4 bb = ((const float4*)be2)[lane];
        float4 o4 = make_float4(dd.x*rs*gg.x+bb.x, dd.y*rs*gg.y+bb.y,
                                dd.z*rs*gg.z+bb.z, dd.w*rs*gg.w+bb.w);
        *(float4*)&out_x[((long)rowbase + row)*128 + lane*4] = o4;
        __half2 ha = __floats2half2_rn(o4.x, o4.y);
        __half2 hb = __floats2half2_rn(o4.z, o4.w);
        uint2 u;
        u.x = *reinterpret_cast<uint32_t*>(&ha);
        u.y = *reinterpret_cast<uint32_t*>(&hb);
        *reinterpret_cast<uint2*>(&x1h[row*136 + lane*4]) = u;
    }
    __syncthreads();

    // ---- stage D: xi = x2@Wei ; xj = x2@Wej
    for (int which = 0; which < 2; which++) {
        if (which) __syncthreads();
#pragma unroll
        for (int it = 0; it < 8; it++) {
            int idx = tid + it * 256;
            int r = idx >> 4, c8 = idx & 15;
            cp16(Bb + (uint32_t)((r*136 + c8*8)*2),
                 (which ? g_wej : g_wei) + r*128 + c8*8);
        }
        cp_commit(); cp_wait();
        __syncthreads();
        zacc(acc);
        gmma_g(X1Hb, 136, Bb, R0, C0, lm_r, lm_c, acc);
        float* dst = which ? g_xj : g_xi;
#pragma unroll
        for (int i = 0; i < 2; i++)
#pragma unroll
            for (int j = 0; j < 4; j++) {
                int cl = C0 + 8*j + 2*tg;
                int lr0 = R0 + 16*i + g, lr1 = lr0 + 8;
                *(float2*)&dst[((long)rowbase + lr0)*128 + cl] = make_float2(acc[i][j][0], acc[i][j][1]);
                *(float2*)&dst[((long)rowbase + lr1)*128 + cl] = make_float2(acc[i][j][2], acc[i][j][3]);
            }
    }
}

// ---------------- edge_out broadcast ----------------
__global__ void edge_out_kernel(const float* __restrict__ b_edge, float* __restrict__ dst) {
    long gid = (long)blockIdx.x * blockDim.x + threadIdx.x;
    int e4 = (int)(gid & 31);
    long rem = gid >> 5;
    int j = (int)(rem % NN);
    long rem2 = rem / NN;
    int i = (int)(rem2 % NN);
    int b = (int)(rem2 / NN);
    float4 xi = ((const float4*)g_xi)[(b * NN + i) * 32 + e4];
    float4 xj = ((const float4*)g_xj)[(b * NN + j) * 32 + e4];
    float4 be = ((const float4*)b_edge)[e4];
    float4 o;
    o.x = xi.x + xj.x + be.x;
    o.y = xi.y + xj.y + be.y;
    o.z = xi.z + xj.z + be.z;
    o.w = xi.w + xj.w + be.w;
    __stcs(&((float4*)dst)[gid], o);
}

// ---------------- launch ----------------
extern "C" void kernel_launch(void* const* d_in, const int* in_sizes, int n_in,
                              void* d_out, int out_size) {
    const float* node   = (const float*)d_in[0];
    const float* edge   = (const float*)d_in[1];
    const float* Wqi = (const float*)d_in[2];  const float* bqi = (const float*)d_in[3];
    const float* Wki = (const float*)d_in[4];  const float* bki = (const float*)d_in[5];
    const float* Wvi = (const float*)d_in[6];  const float* bvi = (const float*)d_in[7];
    const float* Wqo = (const float*)d_in[8];  const float* bqo = (const float*)d_in[9];
    const float* Wko = (const float*)d_in[10]; const float* bko = (const float*)d_in[11];
    const float* Wvo = (const float*)d_in[12]; const float* bvo = (const float*)d_in[13];
    const float* Wpi = (const float*)d_in[14]; const float* bpi = (const float*)d_in[15];
    const float* Wpo = (const float*)d_in[16]; const float* bpo = (const float*)d_in[17];
    const float* Wf1 = (const float*)d_in[18]; const float* bf1 = (const float*)d_in[19];
    const float* Wf2 = (const float*)d_in[20]; const float* bf2 = (const float*)d_in[21];
    const float* g1  = (const float*)d_in[22]; const float* be1 = (const float*)d_in[23];
    const float* g2  = (const float*)d_in[24]; const float* be2 = (const float*)d_in[25];
    const float* Wedge = (const float*)d_in[26];
    const float* bedge = (const float*)d_in[27];
    float* out = (float*)d_out;

    cudaFuncSetAttribute(fused_edge_kernel,
                         cudaFuncAttributeMaxDynamicSharedMemorySize, 104448);
    cudaFuncSetAttribute(node_chain_kernel,
                         cudaFuncAttributeMaxDynamicSharedMemorySize, NSM_TOTAL);

    // precompute
    cvtw_kernel<<<dim3(256, 8), 256>>>(Wqi, Wki, Wqo, Wko, Wf1, Wf2, Wedge);
    comp_kernel<<<dim3(1024, 2), 128>>>(Wvi, Wpi, Wvo, Wpo);
    cbias_kernel<<<1, 128>>>(bvi, Wpi, bpi, bvo, Wpo, bpo);

    // 1) q/k projections + scores
    fused_edge_kernel<<<ROWS_TOTAL / 128, 256, 104448>>>(edge, bqi, bki, bqo, bko);

    // 2) fused softmax + weighted edge sums
    wsum_kernel<<<dim3(BB * NN, 2), 256>>>(edge);

    // 3) full node chain in one kernel
    node_chain_kernel<<<BB * NN / 64, 256, NSM_TOTAL>>>(node, bf1, bf2, g1, be1, g2, be2, out);

    // 4) edge_out broadcast
    edge_out_kernel<<<(BB * NN * NN * DD / 4) / 256, 256>>>(bedge, out + BB * NN * DD);
}

// round 9
// speedup vs baseline: 39.6439x; 1.1836x over previous
#include <cuda_runtime.h>
#include <cuda_fp16.h>
#include <cstdint>

#define BB 8
#define NN 160
#define DD 128
#define HH 8
#define ROWS_TOTAL (BB*NN*NN)   // 204800

// ---------------- scratch ----------------
__device__ float g_s_in [ROWS_TOTAL*HH];     // [b, j, h, i] contiguous in i
__device__ float g_s_out[ROWS_TOTAL*HH];     // [b, i, h, j] contiguous in j
__device__ float g_we_in [BB*NN*1024];       // [bn][h*128+c]
__device__ float g_we_out[BB*NN*1024];
__device__ float g_oi[BB*NN*DD];             // headwise we@Wv (in)
__device__ float g_oo[BB*NN*DD];
__device__ float g_xi[BB*NN*DD];
__device__ float g_xj[BB*NN*DD];
__device__ float g_cbias[DD];
// pre-converted half weights
__device__ __align__(16) __half g_whqk[4][128*136];   // (qi,ki,qo,ko), stride 136
__device__ __align__(16) __half g_wf1[128*512];
__device__ __align__(16) __half g_wf2[512*128];
__device__ __align__(16) __half g_wei[128*128];
__device__ __align__(16) __half g_wej[128*128];
__device__ __align__(16) __half g_wpi[128*128];
__device__ __align__(16) __half g_wpo[128*128];

// ---------------- mma/ldmatrix helpers ----------------
#define MMA_F16(d, a0,a1,a2,a3, b0,b1)                                       \
    asm("mma.sync.aligned.m16n8k16.row.col.f32.f16.f16.f32 "                 \
        "{%0,%1,%2,%3}, {%4,%5,%6,%7}, {%8,%9}, {%0,%1,%2,%3};"              \
        : "+f"(d[0]),"+f"(d[1]),"+f"(d[2]),"+f"(d[3])                        \
        : "r"(a0),"r"(a1),"r"(a2),"r"(a3),"r"(b0),"r"(b1))

__device__ __forceinline__ void ldsm4(uint32_t addr, uint32_t& r0, uint32_t& r1,
                                      uint32_t& r2, uint32_t& r3) {
    asm volatile("ldmatrix.sync.aligned.m8n8.x4.shared.b16 {%0,%1,%2,%3}, [%4];"
                 : "=r"(r0),"=r"(r1),"=r"(r2),"=r"(r3) : "r"(addr));
}
__device__ __forceinline__ void ldsm4t(uint32_t addr, uint32_t& r0, uint32_t& r1,
                                       uint32_t& r2, uint32_t& r3) {
    asm volatile("ldmatrix.sync.aligned.m8n8.x4.trans.shared.b16 {%0,%1,%2,%3}, [%4];"
                 : "=r"(r0),"=r"(r1),"=r"(r2),"=r"(r3) : "r"(addr));
}
__device__ __forceinline__ void cp16(uint32_t dst, const void* src) {
    asm volatile("cp.async.cg.shared.global [%0], [%1], 16;" :: "r"(dst), "l"(src));
}
__device__ __forceinline__ void cp_commit() { asm volatile("cp.async.commit_group;"); }
__device__ __forceinline__ void cp_wait()   { asm volatile("cp.async.wait_group 0;" ::: "memory"); }

// ---------------- precompute kernels ----------------
__global__ void cvtw_kernel(const float* __restrict__ Wqi, const float* __restrict__ Wki,
                            const float* __restrict__ Wqo, const float* __restrict__ Wko,
                            const float* __restrict__ Wf1, const float* __restrict__ Wf2,
                            const float* __restrict__ We,
                            const float* __restrict__ Wpi, const float* __restrict__ Wpo) {
    int t = blockIdx.x * 256 + threadIdx.x;
    int reg = blockIdx.y;
    if (reg < 4) {
        if (t < 16384) {
            const float* src = (reg==0)?Wqi:(reg==1)?Wki:(reg==2)?Wqo:Wko;
            int r = t >> 7, c = t & 127;
            g_whqk[reg][r*136 + c] = __float2half_rn(src[t]);
        }
    } else if (reg == 4) { g_wf1[t] = __float2half_rn(Wf1[t]); }
    else if (reg == 5)   { g_wf2[t] = __float2half_rn(Wf2[t]); }
    else if (reg == 6)   { if (t < 16384) g_wei[t] = __float2half_rn(We[t]); }
    else if (reg == 7)   { if (t < 16384) g_wej[t] = __float2half_rn(We[16384 + t]); }
    else if (reg == 8)   { if (t < 16384) g_wpi[t] = __float2half_rn(Wpi[t]); }
    else                 { if (t < 16384) g_wpo[t] = __float2half_rn(Wpo[t]); }
}

__global__ void cbias_kernel(const float* bvi, const float* Wpi, const float* bpi,
                             const float* bvo, const float* Wpo, const float* bpo) {
    int e = threadIdx.x;
    float s = bpi[e] + bpo[e];
    for (int c = 0; c < 128; c++)
        s += bvi[c]*Wpi[c*128+e] + bvo[c]*Wpo[c*128+e];
    g_cbias[e] = s;
}

// =======================================================================
//  FUSED EDGE q/k kernel (unchanged from R8)
//  smem bytes: W0 [0,34816) W1 [34816,69632) A [69632,104448)
// =======================================================================
__device__ __forceinline__ void prefetch_slab(const __half* src, uint32_t dstb, int tid) {
#pragma unroll
    for (int it = 0; it < 9; it++) {
        int idx = tid + it * 256;
        if (idx < 2176) cp16(dstb + idx*16, src + idx*8);
    }
    cp_commit();
}

__device__ __forceinline__ void qpass(uint32_t Ab, uint32_t Wb, int R0, int C0,
                                      int lm_r, int lm_c, float (&acc)[2][8][4]) {
#pragma unroll
    for (int i = 0; i < 2; i++)
#pragma unroll
        for (int j = 0; j < 8; j++)
#pragma unroll
            for (int t = 0; t < 4; t++) acc[i][j][t] = 0.f;
#pragma unroll 1
    for (int kc = 0; kc < 8; kc++) {
        int k0 = kc * 16;
        uint32_t a[2][4];
#pragma unroll
        for (int i = 0; i < 2; i++)
            ldsm4(Ab + (uint32_t)(((R0 + 16*i + lm_r)*136 + k0 + lm_c)*2),
                  a[i][0], a[i][1], a[i][2], a[i][3]);
        uint32_t b[8][2];
#pragma unroll
        for (int jj = 0; jj < 4; jj++) {
            uint32_t r0,r1,r2,r3;
            ldsm4t(Wb + (uint32_t)(((k0 + lm_r)*136 + C0 + 16*jj + lm_c)*2), r0,r1,r2,r3);
            b[2*jj][0]=r0; b[2*jj][1]=r1; b[2*jj+1][0]=r2; b[2*jj+1][1]=r3;
        }
#pragma unroll
        for (int i = 0; i < 2; i++)
#pragma unroll
            for (int j = 0; j < 8; j++)
                MMA_F16(acc[i][j], a[i][0],a[i][1],a[i][2],a[i][3], b[j][0], b[j][1]);
    }
}

__device__ __forceinline__ void pack_q(const float (&acc)[2][8][4],
                                       const float* __restrict__ bq,
                                       int C0, int tg, uint32_t (&qh)[2][8][2]) {
#pragma unroll
    for (int i = 0; i < 2; i++)
#pragma unroll
        for (int j = 0; j < 8; j++) {
            int colg = C0 + 8*j + 2*tg;
            float bq0 = bq[colg], bq1 = bq[colg+1];
            __half2 lo = __floats2half2_rn(acc[i][j][0]+bq0, acc[i][j][1]+bq1);
            __half2 hi = __floats2half2_rn(acc[i][j][2]+bq0, acc[i][j][3]+bq1);
            qh[i][j][0] = *reinterpret_cast<uint32_t*>(&lo);
            qh[i][j][1] = *reinterpret_cast<uint32_t*>(&hi);
        }
}

__device__ __forceinline__ void kpass_pair(uint32_t Ab, uint32_t Wb,
        const uint32_t (&qh)[2][8][2],
        const float* __restrict__ bk,
        float* __restrict__ sdst, int swap,
        int rowbase, int R0, int C0, int g, int tg, int lm_r, int lm_c) {
#pragma unroll 1
    for (int op = 0; op < 2; op++) {
        float acck[2][4][4];
#pragma unroll
        for (int i = 0; i < 2; i++)
#pragma unroll
            for (int j = 0; j < 4; j++)
#pragma unroll
                for (int t = 0; t < 4; t++) acck[i][j][t] = 0.f;
#pragma unroll 1
        for (int kc = 0; kc < 8; kc++) {
            int k0 = kc * 16;
            uint32_t a[2][4];
#pragma unroll
            for (int i = 0; i < 2; i++)
                ldsm4(Ab + (uint32_t)(((R0 + 16*i + lm_r)*136 + k0 + lm_c)*2),
                      a[i][0], a[i][1], a[i][2], a[i][3]);
#pragma unroll
            for (int p = 0; p < 2; p++) {
                int jj = 2*op + p;
                uint32_t b0,b1,b2,b3;
                ldsm4t(Wb + (uint32_t)(((k0 + lm_r)*136 + C0 + 16*jj + lm_c)*2), b0,b1,b2,b3);
#pragma unroll
                for (int i = 0; i < 2; i++) {
                    MMA_F16(acck[i][2*p],   a[i][0],a[i][1],a[i][2],a[i][3], b0, b1);
                    MMA_F16(acck[i][2*p+1], a[i][0],a[i][1],a[i][2],a[i][3], b2, b3);
                }
            }
        }
#pragma unroll
        for (int i = 0; i < 2; i++)
#pragma unroll
            for (int p = 0; p < 2; p++) {
                float sc0 = 0.f, sc1 = 0.f;
#pragma unroll
                for (int j2 = 0; j2 < 2; j2++) {
                    int colg = C0 + 16*(2*op+p) + 8*j2 + 2*tg;
                    float bk0 = bk[colg], bk1 = bk[colg+1];
                    const uint32_t* q = qh[i][4*op + 2*p + j2];
                    float2 qlo = __half22float2(*reinterpret_cast<const __half2*>(&q[0]));
                    float2 qhi = __half22float2(*reinterpret_cast<const __half2*>(&q[1]));
                    const float* k = acck[i][2*p + j2];
                    sc0 += qlo.x*(k[0]+bk0) + qlo.y*(k[1]+bk1);
                    sc1 += qhi.x*(k[2]+bk0) + qhi.y*(k[3]+bk1);
                }
                sc0 += __shfl_xor_sync(0xffffffffu, sc0, 1);
                sc0 += __shfl_xor_sync(0xffffffffu, sc0, 2);
                sc1 += __shfl_xor_sync(0xffffffffu, sc1, 1);
                sc1 += __shfl_xor_sync(0xffffffffu, sc1, 2);
                if (tg == 0) {
                    int h = (C0 >> 4) + 2*op + p;
#pragma unroll
                    for (int hf = 0; hf < 2; hf++) {
                        float v = hf ? sc1 : sc0;
                        int grow = rowbase + R0 + 16*i + 8*hf + g;
                        int b = grow / (NN*NN);
                        int rem = grow - b*NN*NN;
                        int ii = rem / NN;
                        int jn = rem - ii*NN;
                        int r1 = swap ? jn : ii;
                        int r2 = swap ? ii : jn;
                        sdst[((b*NN + r1)*HH + h)*NN + r2] = v * 0.25f;
                    }
                }
            }
    }
}

__global__ void __launch_bounds__(256, 2) fused_edge_kernel(
    const float* __restrict__ edge,
    const float* __restrict__ bqi, const float* __restrict__ bki,
    const float* __restrict__ bqo, const float* __restrict__ bko)
{
    extern __shared__ __half smh[];
    uint32_t sb = (uint32_t)__cvta_generic_to_shared(smh);
    uint32_t W0b = sb, W1b = sb + 34816, Ab = sb + 69632;
    __half* A_h = smh + 34816;

    int tid = threadIdx.x, lane = tid & 31, wid = tid >> 5;
    int g = lane >> 2, tg = lane & 3;
    int lm_r = ((lane >> 3) & 1) * 8 + (lane & 7);
    int lm_c = (lane >> 4) * 8;
    int R0 = (wid >> 1) * 32, C0 = (wid & 1) * 64;
    int rowbase = blockIdx.x * 128;

    prefetch_slab(g_whqk[0], W0b, tid);

    const float4* Eg = (const float4*)(edge + (long)rowbase * DD);
#pragma unroll
    for (int it = 0; it < 16; it++) {
        int idx = tid + it * 256;
        int r = idx >> 5, c4 = idx & 31;
        float4 v = Eg[idx];
        __half2 h01 = __floats2half2_rn(v.x, v.y);
        __half2 h23 = __floats2half2_rn(v.z, v.w);
        uint2 u;
        u.x = *reinterpret_cast<uint32_t*>(&h01);
        u.y = *reinterpret_cast<uint32_t*>(&h23);
        *reinterpret_cast<uint2*>(&A_h[r*136 + c4*4]) = u;
    }
    cp_wait(); __syncthreads();
    prefetch_slab(g_whqk[1], W1b, tid);

    uint32_t qh[2][8][2];
    {
        float accQ[2][8][4];
        qpass(Ab, W0b, R0, C0, lm_r, lm_c, accQ);
        pack_q(accQ, bqi, C0, tg, qh);
    }
    cp_wait(); __syncthreads();
    prefetch_slab(g_whqk[2], W0b, tid);
    kpass_pair(Ab, W1b, qh, bki, g_s_in, 1, rowbase, R0, C0, g, tg, lm_r, lm_c);

    cp_wait(); __syncthreads();
    prefetch_slab(g_whqk[3], W1b, tid);
    {
        float accQ[2][8][4];
        qpass(Ab, W0b, R0, C0, lm_r, lm_c, accQ);
        pack_q(accQ, bqo, C0, tg, qh);
    }
    cp_wait(); __syncthreads();
    kpass_pair(Ab, W1b, qh, bko, g_s_out, 0, rowbase, R0, C0, g, tg, lm_r, lm_c);
}

// =======================================================================
//  wsum: softmax + MMA reduction  we[bn][h*128+e] = sum_k a[h,k]*E[k,e]
// =======================================================================
__global__ void __launch_bounds__(256) wsum_kernel(const float* __restrict__ edge) {
    __shared__ __align__(16) __half sE[160*136];
    __shared__ __align__(16) __half sA[16*168];
    int tid = threadIdx.x, lane = tid & 31, wid = tid >> 5;
    int bn = blockIdx.x, dir = blockIdx.y;
    int b = bn / NN, n = bn % NN;

    // load edge slice (160 x 128) as fp16; warp wid handles rows wid, wid+8, ...
    long gbase; long rstride;
    if (dir) { gbase = (long)bn * NN * DD;                 rstride = DD; }
    else     { gbase = ((long)b * NN * NN + n) * DD;       rstride = (long)NN * DD; }
#pragma unroll 4
    for (int rr = 0; rr < 20; rr++) {
        int row = wid + rr * 8;
        float4 v = __ldcs((const float4*)&edge[gbase + (long)row * rstride + lane * 4]);
        __half2 h01 = __floats2half2_rn(v.x, v.y);
        __half2 h23 = __floats2half2_rn(v.z, v.w);
        uint2 u;
        u.x = *reinterpret_cast<uint32_t*>(&h01);
        u.y = *reinterpret_cast<uint32_t*>(&h23);
        *reinterpret_cast<uint2*>(&sE[row*136 + lane*4]) = u;
    }

    // softmax: warp wid owns head wid
    {
        const float* s = dir ? g_s_out : g_s_in;
        long sbase = (long)bn * (HH*NN) + (long)wid * NN;
        float v[5];
#pragma unroll
        for (int t = 0; t < 5; t++) v[t] = s[sbase + lane + 32*t];
        float mx = v[0];
#pragma unroll
        for (int t = 1; t < 5; t++) mx = fmaxf(mx, v[t]);
#pragma unroll
        for (int o = 16; o > 0; o >>= 1) mx = fmaxf(mx, __shfl_xor_sync(0xffffffffu, mx, o));
        float sum = 0.f;
#pragma unroll
        for (int t = 0; t < 5; t++) { v[t] = __expf(v[t] - mx); sum += v[t]; }
#pragma unroll
        for (int o = 16; o > 0; o >>= 1) sum += __shfl_xor_sync(0xffffffffu, sum, o);
        float inv = __frcp_rn(sum);
#pragma unroll
        for (int t = 0; t < 5; t++) sA[wid*168 + lane + 32*t] = __float2half_rn(v[t] * inv);
        // zero pad row (wid+8) — multiplies into discarded C rows, keep finite
        for (int i = lane; i < 168; i += 32) sA[(wid + 8)*168 + i] = __ushort_as_half(0);
        if (lane < 8) sA[wid*168 + 160 + lane] = __ushort_as_half(0);
    }
    __syncthreads();

    // MMA: warp wid -> output cols [16*wid, 16*wid+16)
    uint32_t Eb = (uint32_t)__cvta_generic_to_shared(sE);
    uint32_t Ab = (uint32_t)__cvta_generic_to_shared(sA);
    int lm_r = ((lane >> 3) & 1) * 8 + (lane & 7);
    int lm_c = (lane >> 4) * 8;
    float acc[2][4];
#pragma unroll
    for (int j = 0; j < 2; j++)
#pragma unroll
        for (int t = 0; t < 4; t++) acc[j][t] = 0.f;
#pragma unroll
    for (int kc = 0; kc < 10; kc++) {
        int k0 = kc * 16;
        uint32_t a0,a1,a2,a3;
        ldsm4(Ab + (uint32_t)((lm_r*168 + k0 + lm_c)*2), a0,a1,a2,a3);
        uint32_t b0,b1,b2,b3;
        ldsm4t(Eb + (uint32_t)(((k0 + lm_r)*136 + wid*16 + lm_c)*2), b0,b1,b2,b3);
        MMA_F16(acc[0], a0,a1,a2,a3, b0,b1);
        MMA_F16(acc[1], a0,a1,a2,a3, b2,b3);
    }
    // epilogue: row g = head, cols 16*wid + 8*j2 + 2*tg (rows g+8 discarded)
    int g = lane >> 2, tg = lane & 3;
    float* we = dir ? g_we_out : g_we_in;
#pragma unroll
    for (int j2 = 0; j2 < 2; j2++)
        *(float2*)&we[(long)bn*1024 + g*128 + wid*16 + 8*j2 + 2*tg] =
            make_float2(acc[j2][0], acc[j2][1]);
}

// =======================================================================
//  ov: headwise  o[row][e] = sum_k we[row][h(e)*128+k] * Wv[k][e]
// =======================================================================
__global__ void __launch_bounds__(128) ov_kernel(const float* __restrict__ Wvi,
                                                 const float* __restrict__ Wvo) {
    __shared__ float swe[8*1056];   // 8 rows, head stride 132
    int dir = blockIdx.y;
    int rb = blockIdx.x * 8;
    const float* we = dir ? g_we_out : g_we_in;
    const float* Wv = dir ? Wvo : Wvi;
    int tid = threadIdx.x;
    for (int i = tid; i < 2048; i += 128) {
        int r = i >> 8;          // 256 float4 per row
        int c4 = i & 255;
        float4 v = ((const float4*)(we + (long)(rb + r) * 1024))[c4];
        int c = c4 * 4;
        *(float4*)&swe[r*1056 + (c >> 7)*132 + (c & 127)] = v;
    }
    __syncthreads();
    int e = tid, h = e >> 4;
    float acc[8] = {0,0,0,0,0,0,0,0};
#pragma unroll 4
    for (int k = 0; k < 128; k++) {
        float w = Wv[k*128 + e];
        int s = h*132 + k;
#pragma unroll
        for (int r = 0; r < 8; r++) acc[r] += swe[r*1056 + s] * w;
    }
    float* dst = dir ? g_oo : g_oi;
#pragma unroll
    for (int r = 0; r < 8; r++) dst[(long)(rb + r)*128 + e] = acc[r];
}

// =======================================================================
//  node_chain: x1 = LN(oi@Wpi + oo@Wpo + cbias + node) -> ff -> x2 -> xi/xj
// =======================================================================
#define NSM_B    0
#define NSM_A    34816
#define NSM_CS   52224
#define NSM_X1H  86016
#define NSM_X1F  103424
#define NSM_FFH  136192
#define NSM_TOTAL 202752

__device__ __forceinline__ void gmma_g(uint32_t Ab, int astride, uint32_t Bb,
                                       int R0, int C0, int lm_r, int lm_c,
                                       float (&acc)[2][4][4]) {
#pragma unroll 1
    for (int kc = 0; kc < 8; kc++) {
        int k0 = kc * 16;
        uint32_t a[2][4];
#pragma unroll
        for (int i = 0; i < 2; i++)
            ldsm4(Ab + (uint32_t)(((R0 + 16*i + lm_r)*astride + k0 + lm_c)*2),
                  a[i][0], a[i][1], a[i][2], a[i][3]);
        uint32_t b[4][2];
#pragma unroll
        for (int jj = 0; jj < 2; jj++) {
            uint32_t r0,r1,r2,r3;
            ldsm4t(Bb + (uint32_t)(((k0 + lm_r)*136 + C0 + 16*jj + lm_c)*2), r0,r1,r2,r3);
            b[2*jj][0]=r0; b[2*jj][1]=r1; b[2*jj+1][0]=r2; b[2*jj+1][1]=r3;
        }
#pragma unroll
        for (int i = 0; i < 2; i++)
#pragma unroll
            for (int j = 0; j < 4; j++)
                MMA_F16(acc[i][j], a[i][0],a[i][1],a[i][2],a[i][3], b[j][0], b[j][1]);
    }
}

__device__ __forceinline__ void zacc(float (&acc)[2][4][4]) {
#pragma unroll
    for (int i = 0; i < 2; i++)
#pragma unroll
        for (int j = 0; j < 4; j++)
#pragma unroll
            for (int t = 0; t < 4; t++) acc[i][j][t] = 0.f;
}

__global__ void __launch_bounds__(256) node_chain_kernel(
    const float* __restrict__ node,
    const float* __restrict__ bf1, const float* __restrict__ bf2,
    const float* __restrict__ g1,  const float* __restrict__ be1,
    const float* __restrict__ g2,  const float* __restrict__ be2,
    float* __restrict__ out_x)
{
    extern __shared__ char smc[];
    uint32_t sb = (uint32_t)__cvta_generic_to_shared(smc);
    uint32_t Bb = sb + NSM_B, Ab = sb + NSM_A, X1Hb = sb + NSM_X1H, FFHb = sb + NSM_FFH;
    __half* A_h  = (__half*)(smc + NSM_A);
    float*  Cs   = (float*)(smc + NSM_CS);
    __half* x1h  = (__half*)(smc + NSM_X1H);
    float*  x1f  = (float*)(smc + NSM_X1F);
    __half* ffh  = (__half*)(smc + NSM_FFH);
    int tid = threadIdx.x, lane = tid & 31, wid = tid >> 5;
    int g = lane >> 2, tg = lane & 3;
    int lm_r = ((lane >> 3) & 1) * 8 + (lane & 7);
    int lm_c = (lane >> 4) * 8;
    int R0 = (wid >> 2) * 32, C0 = (wid & 3) * 32;
    int rowbase = blockIdx.x * 64;

    float acc[2][4][4];

    // ---- stage A: t = oi@Wpi + oo@Wpo + cbias + node ; x1 = LN(t)
    zacc(acc);
    for (int c = 0; c < 2; c++) {
        const float* Ap = c ? g_oo : g_oi;
        const __half* Bp = c ? g_wpo : g_wpi;
        if (c) __syncthreads();
#pragma unroll
        for (int it = 0; it < 8; it++) {
            int idx = tid + it * 256;
            int r = idx >> 4, c8 = idx & 15;
            cp16(Bb + (uint32_t)((r*136 + c8*8)*2), Bp + r*128 + c8*8);
        }
        cp_commit();
#pragma unroll
        for (int it = 0; it < 8; it++) {
            int idx = tid + it * 256;
            int r = idx >> 5, c4 = idx & 31;
            float4 v = *(const float4*)&Ap[(long)(rowbase + r)*128 + c4*4];
            __half2 h01 = __floats2half2_rn(v.x, v.y);
            __half2 h23 = __floats2half2_rn(v.z, v.w);
            uint2 u;
            u.x = *reinterpret_cast<uint32_t*>(&h01);
            u.y = *reinterpret_cast<uint32_t*>(&h23);
            *reinterpret_cast<uint2*>(&A_h[r*136 + c4*4]) = u;
        }
        cp_wait();
        __syncthreads();
        gmma_g(Ab, 136, Bb, R0, C0, lm_r, lm_c, acc);
    }
#pragma unroll
    for (int i = 0; i < 2; i++)
#pragma unroll
        for (int j = 0; j < 4; j++) {
            int cl = C0 + 8*j + 2*tg;
            int lr0 = R0 + 16*i + g, lr1 = lr0 + 8;
            float2 n0 = *(const float2*)&node[((long)rowbase + lr0)*128 + cl];
            float2 n1 = *(const float2*)&node[((long)rowbase + lr1)*128 + cl];
            float b0 = g_cbias[cl], b1 = g_cbias[cl+1];
            *(float2*)&Cs[lr0*132 + cl] = make_float2(acc[i][j][0]+b0+n0.x, acc[i][j][1]+b1+n0.y);
            *(float2*)&Cs[lr1*132 + cl] = make_float2(acc[i][j][2]+b0+n1.x, acc[i][j][3]+b1+n1.y);
        }
    __syncthreads();
#pragma unroll
    for (int r = 0; r < 8; r++) {
        int row = wid * 8 + r;
        float4 v = *(const float4*)&Cs[row*132 + lane*4];
        float s = v.x + v.y + v.z + v.w;
#pragma unroll
        for (int o = 16; o > 0; o >>= 1) s += __shfl_xor_sync(0xffffffffu, s, o);
        float mean = s * (1.f/128.f);
        float4 dd = make_float4(v.x-mean, v.y-mean, v.z-mean, v.w-mean);
        float q = dd.x*dd.x + dd.y*dd.y + dd.z*dd.z + dd.w*dd.w;
#pragma unroll
        for (int o = 16; o > 0; o >>= 1) q += __shfl_xor_sync(0xffffffffu, q, o);
        float rs = rsqrtf(q * (1.f/128.f) + 1e-5f);
        float4 gg = ((const float4*)g1)[lane];
        float4 bb = ((const float4*)be1)[lane];
        float4 o4 = make_float4(dd.x*rs*gg.x+bb.x, dd.y*rs*gg.y+bb.y,
                                dd.z*rs*gg.z+bb.z, dd.w*rs*gg.w+bb.w);
        *(float4*)&x1f[row*128 + lane*4] = o4;
        __half2 ha = __floats2half2_rn(o4.x, o4.y);
        __half2 hb = __floats2half2_rn(o4.z, o4.w);
        uint2 u;
        u.x = *reinterpret_cast<uint32_t*>(&ha);
        u.y = *reinterpret_cast<uint32_t*>(&hb);
        *reinterpret_cast<uint2*>(&x1h[row*136 + lane*4]) = u;
    }
    __syncthreads();

    // ---- stage B: ff = relu(x1@Wf1 + bf1)
    for (int nc = 0; nc < 4; nc++) {
        if (nc) __syncthreads();
#pragma unroll
        for (int it = 0; it < 8; it++) {
            int idx = tid + it * 256;
            int r = idx >> 4, c8 = idx & 15;
            cp16(Bb + (uint32_t)((r*136 + c8*8)*2), g_wf1 + r*512 + nc*128 + c8*8);
        }
        cp_commit(); cp_wait();
        __syncthreads();
        zacc(acc);
        gmma_g(X1Hb, 136, Bb, R0, C0, lm_r, lm_c, acc);
#pragma unroll
        for (int i = 0; i < 2; i++)
#pragma unroll
            for (int j = 0; j < 4; j++) {
                int cl = C0 + 8*j + 2*tg;
                int cg_ = nc*128 + cl;
                float b0 = bf1[cg_], b1 = bf1[cg_+1];
                int lr0 = R0 + 16*i + g, lr1 = lr0 + 8;
                __half2 v0 = __floats2half2_rn(fmaxf(acc[i][j][0]+b0, 0.f), fmaxf(acc[i][j][1]+b1, 0.f));
                __half2 v1 = __floats2half2_rn(fmaxf(acc[i][j][2]+b0, 0.f), fmaxf(acc[i][j][3]+b1, 0.f));
                *reinterpret_cast<uint32_t*>(&ffh[lr0*520 + cg_]) = *reinterpret_cast<uint32_t*>(&v0);
                *reinterpret_cast<uint32_t*>(&ffh[lr1*520 + cg_]) = *reinterpret_cast<uint32_t*>(&v1);
            }
    }
    __syncthreads();

    // ---- stage C: t2 = ff@Wf2 + bf2 + x1 ; x2 = LN(t2)
    zacc(acc);
    for (int c = 0; c < 4; c++) {
        int kb = c << 7;
        __syncthreads();
#pragma unroll
        for (int it = 0; it < 8; it++) {
            int idx = tid + it * 256;
            int r = idx >> 4, c8 = idx & 15;
            cp16(Bb + (uint32_t)((r*136 + c8*8)*2), g_wf2 + (long)(kb + r)*128 + c8*8);
        }
        cp_commit(); cp_wait();
        __syncthreads();
        gmma_g(FFHb + (uint32_t)(kb*2), 520, Bb, R0, C0, lm_r, lm_c, acc);
    }
#pragma unroll
    for (int i = 0; i < 2; i++)
#pragma unroll
        for (int j = 0; j < 4; j++) {
            int cl = C0 + 8*j + 2*tg;
            float b0 = bf2[cl], b1 = bf2[cl+1];
            int lr0 = R0 + 16*i + g, lr1 = lr0 + 8;
            float2 r0v = *(const float2*)&x1f[lr0*128 + cl];
            float2 r1v = *(const float2*)&x1f[lr1*128 + cl];
            *(float2*)&Cs[lr0*132 + cl] = make_float2(acc[i][j][0]+b0+r0v.x, acc[i][j][1]+b1+r0v.y);
            *(float2*)&Cs[lr1*132 + cl] = make_float2(acc[i][j][2]+b0+r1v.x, acc[i][j][3]+b1+r1v.y);
        }
    __syncthreads();
#pragma unroll
    for (int r = 0; r < 8; r++) {
        int row = wid * 8 + r;
        float4 v = *(const float4*)&Cs[row*132 + lane*4];
        float s = v.x + v.y + v.z + v.w;
#pragma unroll
        for (int o = 16; o > 0; o >>= 1) s += __shfl_xor_sync(0xffffffffu, s, o);
        float mean = s * (1.f/128.f);
        float4 dd = make_float4(v.x-mean, v.y-mean, v.z-mean, v.w-mean);
        float q = dd.x*dd.x + dd.y*dd.y + dd.z*dd.z + dd.w*dd.w;
#pragma unroll
        for (int o = 16; o > 0; o >>= 1) q += __shfl_xor_sync(0xffffffffu, q, o);
        float rs = rsqrtf(q * (1.f/128.f) + 1e-5f);
        float4 gg = ((const float4*)g2)[lane];
        float4 bb = ((const float4*)be2)[lane];
        float4 o4 = make_float4(dd.x*rs*gg.x+bb.x, dd.y*rs*gg.y+bb.y,
                                dd.z*rs*gg.z+bb.z, dd.w*rs*gg.w+bb.w);
        *(float4*)&out_x[((long)rowbase + row)*128 + lane*4] = o4;
        __half2 ha = __floats2half2_rn(o4.x, o4.y);
        __half2 hb = __floats2half2_rn(o4.z, o4.w);
        uint2 u;
        u.x = *reinterpret_cast<uint32_t*>(&ha);
        u.y = *reinterpret_cast<uint32_t*>(&hb);
        *reinterpret_cast<uint2*>(&x1h[row*136 + lane*4]) = u;
    }
    __syncthreads();

    // ---- stage D: xi = x2@Wei ; xj = x2@Wej
    for (int which = 0; which < 2; which++) {
        if (which) __syncthreads();
#pragma unroll
        for (int it = 0; it < 8; it++) {
            int idx = tid + it * 256;
            int r = idx >> 4, c8 = idx & 15;
            cp16(Bb + (uint32_t)((r*136 + c8*8)*2),
                 (which ? g_wej : g_wei) + r*128 + c8*8);
        }
        cp_commit(); cp_wait();
        __syncthreads();
        zacc(acc);
        gmma_g(X1Hb, 136, Bb, R0, C0, lm_r, lm_c, acc);
        float* dst = which ? g_xj : g_xi;
#pragma unroll
        for (int i = 0; i < 2; i++)
#pragma unroll
            for (int j = 0; j < 4; j++) {
                int cl = C0 + 8*j + 2*tg;
                int lr0 = R0 + 16*i + g, lr1 = lr0 + 8;
                *(float2*)&dst[((long)rowbase + lr0)*128 + cl] = make_float2(acc[i][j][0], acc[i][j][1]);
                *(float2*)&dst[((long)rowbase + lr1)*128 + cl] = make_float2(acc[i][j][2], acc[i][j][3]);
            }
    }
}

// ---------------- edge_out broadcast ----------------
__global__ void edge_out_kernel(const float* __restrict__ b_edge, float* __restrict__ dst) {
    long gid = (long)blockIdx.x * blockDim.x + threadIdx.x;
    int e4 = (int)(gid & 31);
    long rem = gid >> 5;
    int j = (int)(rem % NN);
    long rem2 = rem / NN;
    int i = (int)(rem2 % NN);
    int b = (int)(rem2 / NN);
    float4 xi = ((const float4*)g_xi)[(b * NN + i) * 32 + e4];
    float4 xj = ((const float4*)g_xj)[(b * NN + j) * 32 + e4];
    float4 be = ((const float4*)b_edge)[e4];
    float4 o;
    o.x = xi.x + xj.x + be.x;
    o.y = xi.y + xj.y + be.y;
    o.z = xi.z + xj.z + be.z;
    o.w = xi.w + xj.w + be.w;
    __stcs(&((float4*)dst)[gid], o);
}

// ---------------- launch ----------------
extern "C" void kernel_launch(void* const* d_in, const int* in_sizes, int n_in,
                              void* d_out, int out_size) {
    const float* node   = (const float*)d_in[0];
    const float* edge   = (const float*)d_in[1];
    const float* Wqi = (const float*)d_in[2];  const float* bqi = (const float*)d_in[3];
    const float* Wki = (const float*)d_in[4];  const float* bki = (const float*)d_in[5];
    const float* Wvi = (const float*)d_in[6];  const float* bvi = (const float*)d_in[7];
    const float* Wqo = (const float*)d_in[8];  const float* bqo = (const float*)d_in[9];
    const float* Wko = (const float*)d_in[10]; const float* bko = (const float*)d_in[11];
    const float* Wvo = (const float*)d_in[12]; const float* bvo = (const float*)d_in[13];
    const float* Wpi = (const float*)d_in[14]; const float* bpi = (const float*)d_in[15];
    const float* Wpo = (const float*)d_in[16]; const float* bpo = (const float*)d_in[17];
    const float* Wf1 = (const float*)d_in[18]; const float* bf1 = (const float*)d_in[19];
    const float* Wf2 = (const float*)d_in[20]; const float* bf2 = (const float*)d_in[21];
    const float* g1  = (const float*)d_in[22]; const float* be1 = (const float*)d_in[23];
    const float* g2  = (const float*)d_in[24]; const float* be2 = (const float*)d_in[25];
    const float* Wedge = (const float*)d_in[26];
    const float* bedge = (const float*)d_in[27];
    float* out = (float*)d_out;

    cudaFuncSetAttribute(fused_edge_kernel,
                         cudaFuncAttributeMaxDynamicSharedMemorySize, 104448);
    cudaFuncSetAttribute(node_chain_kernel,
                         cudaFuncAttributeMaxDynamicSharedMemorySize, NSM_TOTAL);

    // precompute
    cvtw_kernel<<<dim3(256, 10), 256>>>(Wqi, Wki, Wqo, Wko, Wf1, Wf2, Wedge, Wpi, Wpo);
    cbias_kernel<<<1, 128>>>(bvi, Wpi, bpi, bvo, Wpo, bpo);

    // 1) q/k projections + scores
    fused_edge_kernel<<<ROWS_TOTAL / 128, 256, 104448>>>(edge, bqi, bki, bqo, bko);

    // 2) softmax + MMA weighted edge sums
    wsum_kernel<<<dim3(BB * NN, 2), 256>>>(edge);

    // 3) headwise we@Wv -> oi/oo
    ov_kernel<<<dim3(BB * NN / 8, 2), 128>>>(Wvi, Wvo);

    // 4) full node chain
    node_chain_kernel<<<BB * NN / 64, 256, NSM_TOTAL>>>(node, bf1, bf2, g1, be1, g2, be2, out);

    // 5) edge_out broadcast
    edge_out_kernel<<<(BB * NN * NN * DD / 4) / 256, 256>>>(bedge, out + BB * NN * DD);
}